// round 1
// baseline (speedup 1.0000x reference)
#include <cuda_runtime.h>
#include <stdint.h>

#define DD 128
#define NMAX 50000
#define NB ((size_t)NMAX * DD)

// 8 scratch buffers of [NMAX, 128] fp32 (≈205 MB, static device memory — no allocs)
__device__ __align__(16) float g_buf[8 * (size_t)NMAX * DD];
__device__ float g_stats[512];   // [set][{sum,sumsq}][128]
__device__ float g_bnp[512];     // [set][{mu,gamma/std}][128]
__device__ float g_loss;

// ---------------------------------------------------------------------------
// init: agg buffers preloaded with bias rows; zero stats + loss accumulator
// ---------------------------------------------------------------------------
__global__ void init_kernel(float* __restrict__ a1, float* __restrict__ a2,
                            float* __restrict__ ty, float* __restrict__ tx,
                            const float* __restrict__ b, const float* __restrict__ bt,
                            int total) {
    int i = blockIdx.x * blockDim.x + threadIdx.x;
    if (i < 512) g_stats[i] = 0.f;
    if (i == 0) g_loss = 0.f;
    if (i < total) {
        int c = i & 127;
        float vb = b[c], vt = bt[c];
        a1[i] = vb; a2[i] = vb; ty[i] = vt; tx[i] = vt;
    }
}

// ---------------------------------------------------------------------------
// Tiled SGEMM: out[n,128] = f(A)[n,128] @ W[128,128] (+ bias)
// MODE 0: f(A)=A    MODE 1: f(A)=A+Padd    MODE 2: f(A)=PReLU(BN(A))
// Block: 256 threads, tile 64x128, BK=32, 4x8 per-thread microtile.
// ---------------------------------------------------------------------------
template <int MODE>
__global__ __launch_bounds__(256)
void gemm128(const float* __restrict__ A, const float* __restrict__ Padd,
             const float* __restrict__ Wm, const float* __restrict__ bias,
             const float* __restrict__ bnp,     // mu[0..127], g[128..255]
             const float* __restrict__ beta,
             const float* __restrict__ alpha_p,
             float* __restrict__ out, int n) {
    __shared__ float As[32][65];    // [k][m], padded: conflict-free transposed store
    __shared__ float Ws[32][128];   // [k][ncol]

    const int tid = threadIdx.x;
    const int m0 = blockIdx.x * 64;
    const int tm = tid >> 4;        // 0..15 -> 4 rows each
    const int tn = tid & 15;        // 0..15 -> 8 cols each

    float acc[4][8];
#pragma unroll
    for (int i = 0; i < 4; i++)
#pragma unroll
        for (int j = 0; j < 8; j++) acc[i][j] = 0.f;

    float alpha = 0.f;
    if (MODE == 2) alpha = __ldg(alpha_p);

    for (int k0 = 0; k0 < 128; k0 += 32) {
        // ---- A tile: 64 rows x 32 k, transposed into As[k][m] ----
#pragma unroll
        for (int jj = 0; jj < 2; jj++) {
            int f = tid + 256 * jj;
            int row = f >> 3;        // 0..63
            int c4 = f & 7;          // 0..7 (k chunk of 4)
            int gr = m0 + row;
            float4 v = make_float4(0.f, 0.f, 0.f, 0.f);
            if (gr < n) {
                size_t off = (size_t)gr * 128 + k0 + c4 * 4;
                v = *(const float4*)(A + off);
                if (MODE == 1) {
                    float4 p = *(const float4*)(Padd + off);
                    v.x += p.x; v.y += p.y; v.z += p.z; v.w += p.w;
                } else if (MODE == 2) {
                    int kc = k0 + c4 * 4;
                    float4 mu = *(const float4*)(bnp + kc);
                    float4 gg = *(const float4*)(bnp + 128 + kc);
                    float4 be = *(const float4*)(beta + kc);
                    v.x = (v.x - mu.x) * gg.x + be.x;
                    v.y = (v.y - mu.y) * gg.y + be.y;
                    v.z = (v.z - mu.z) * gg.z + be.z;
                    v.w = (v.w - mu.w) * gg.w + be.w;
                    v.x = v.x >= 0.f ? v.x : alpha * v.x;
                    v.y = v.y >= 0.f ? v.y : alpha * v.y;
                    v.z = v.z >= 0.f ? v.z : alpha * v.z;
                    v.w = v.w >= 0.f ? v.w : alpha * v.w;
                }
            }
            As[c4 * 4 + 0][row] = v.x;
            As[c4 * 4 + 1][row] = v.y;
            As[c4 * 4 + 2][row] = v.z;
            As[c4 * 4 + 3][row] = v.w;
        }
        // ---- W tile: 32 k-rows x 128 cols ----
#pragma unroll
        for (int jj = 0; jj < 4; jj++) {
            int f = tid + 256 * jj;
            int row = f >> 5;        // 0..31
            int c4 = f & 31;         // 0..31
            *(float4*)&Ws[row][c4 * 4] =
                *(const float4*)(Wm + (size_t)(k0 + row) * 128 + c4 * 4);
        }
        __syncthreads();

#pragma unroll
        for (int kk = 0; kk < 32; kk++) {
            float a[4];
            a[0] = As[kk][tm * 4 + 0];
            a[1] = As[kk][tm * 4 + 1];
            a[2] = As[kk][tm * 4 + 2];
            a[3] = As[kk][tm * 4 + 3];
            float4 b0 = *(const float4*)&Ws[kk][tn * 8];
            float4 b1 = *(const float4*)&Ws[kk][tn * 8 + 4];
            float br[8] = {b0.x, b0.y, b0.z, b0.w, b1.x, b1.y, b1.z, b1.w};
#pragma unroll
            for (int i = 0; i < 4; i++)
#pragma unroll
                for (int j = 0; j < 8; j++) acc[i][j] += a[i] * br[j];
        }
        __syncthreads();
    }

    // ---- epilogue: optional bias, vectorized store ----
    float bb[8];
    if (bias) {
        float4 bb0 = *(const float4*)(bias + tn * 8);
        float4 bb1 = *(const float4*)(bias + tn * 8 + 4);
        bb[0] = bb0.x; bb[1] = bb0.y; bb[2] = bb0.z; bb[3] = bb0.w;
        bb[4] = bb1.x; bb[5] = bb1.y; bb[6] = bb1.z; bb[7] = bb1.w;
    } else {
#pragma unroll
        for (int j = 0; j < 8; j++) bb[j] = 0.f;
    }
#pragma unroll
    for (int i = 0; i < 4; i++) {
        int gr = m0 + tm * 4 + i;
        if (gr >= n) continue;
        float4 o0, o1;
        o0.x = acc[i][0] + bb[0]; o0.y = acc[i][1] + bb[1];
        o0.z = acc[i][2] + bb[2]; o0.w = acc[i][3] + bb[3];
        o1.x = acc[i][4] + bb[4]; o1.y = acc[i][5] + bb[5];
        o1.z = acc[i][6] + bb[6]; o1.w = acc[i][7] + bb[7];
        *(float4*)(out + (size_t)gr * 128 + tn * 8) = o0;
        *(float4*)(out + (size_t)gr * 128 + tn * 8 + 4) = o1;
    }
}

// ---------------------------------------------------------------------------
// COO SpMM scatter: one warp per edge, float4 per lane, vectorized red.global
// gridDim.y selects which (h, agg) pair (4 GCN aggregations in one launch)
// ---------------------------------------------------------------------------
__global__ __launch_bounds__(256)
void spmm_scatter(const int* __restrict__ erow, const int* __restrict__ ecol,
                  const float* __restrict__ eval,
                  const float* __restrict__ h0, float* __restrict__ a0,
                  const float* __restrict__ h1, float* __restrict__ a1,
                  const float* __restrict__ h2, float* __restrict__ a2,
                  const float* __restrict__ h3, float* __restrict__ a3,
                  int E) {
    int w = (int)((blockIdx.x * (size_t)blockDim.x + threadIdx.x) >> 5);
    if (w >= E) return;
    int lane = threadIdx.x & 31;
    const float* h; float* agg;
    switch (blockIdx.y) {
        case 0:  h = h0; agg = a0; break;
        case 1:  h = h1; agg = a1; break;
        case 2:  h = h2; agg = a2; break;
        default: h = h3; agg = a3; break;
    }
    int r = __ldg(erow + w);
    int c = __ldg(ecol + w);
    float v = __ldg(eval + w);
    float4 m = *(const float4*)(h + (size_t)c * 128 + lane * 4);
    float* dst = agg + (size_t)r * 128 + lane * 4;
    asm volatile("red.global.add.v4.f32 [%0], {%1,%2,%3,%4};"
                 :: "l"(dst), "f"(m.x * v), "f"(m.y * v), "f"(m.z * v), "f"(m.w * v)
                 : "memory");
}

// ---------------------------------------------------------------------------
// embed = x + perb + enc_x2
// ---------------------------------------------------------------------------
__global__ void embed_kernel(const float* __restrict__ x, const float* __restrict__ perb,
                             const float* __restrict__ a2, float* __restrict__ out,
                             int total4) {
    int i = blockIdx.x * blockDim.x + threadIdx.x;
    if (i >= total4) return;
    float4 xv = ((const float4*)x)[i];
    float4 pv = ((const float4*)perb)[i];
    float4 av = ((const float4*)a2)[i];
    float4 o;
    o.x = xv.x + pv.x + av.x; o.y = xv.y + pv.y + av.y;
    o.z = xv.z + pv.z + av.z; o.w = xv.w + pv.w + av.w;
    ((float4*)out)[i] = o;
}

// ---------------------------------------------------------------------------
// BatchNorm stats: per-column sum & sumsq over a 256-row stripe, then atomics
// ---------------------------------------------------------------------------
__global__ void bn_stats(const float* __restrict__ U, int n, int set) {
    int c = threadIdx.x;                 // 128 threads = 128 columns
    int r0 = blockIdx.x * 256;
    int r1 = min(r0 + 256, n);
    float s = 0.f, q = 0.f;
    for (int r = r0; r < r1; r++) {
        float v = U[(size_t)r * 128 + c];
        s += v; q += v * v;
    }
    atomicAdd(&g_stats[set * 256 + c], s);
    atomicAdd(&g_stats[set * 256 + 128 + c], q);
}

__global__ void bn_finalize(const float* __restrict__ gamma, int n) {
    int t = threadIdx.x;                 // 256 threads: 2 sets x 128 cols
    int set = t >> 7, c = t & 127;
    float s = g_stats[set * 256 + c];
    float q = g_stats[set * 256 + 128 + c];
    float mu = s / (float)n;
    float var = q / (float)n - mu * mu;  // biased (train mode)
    float g = gamma[c] * rsqrtf(var + 1e-5f);
    g_bnp[set * 256 + c] = mu;
    g_bnp[set * 256 + 128 + c] = g;
}

// ---------------------------------------------------------------------------
// BYOL loss: sum over rows of (2 - 2*cos(p1,tx)) + (2 - 2*cos(p2,ty))
// one warp per row, grid-stride, block-reduced atomics
// ---------------------------------------------------------------------------
__global__ __launch_bounds__(256)
void byol_loss(const float* __restrict__ p1, const float* __restrict__ tx,
               const float* __restrict__ p2, const float* __restrict__ ty, int n) {
    int gw = (int)((blockIdx.x * (size_t)blockDim.x + threadIdx.x) >> 5);
    int lane = threadIdx.x & 31;
    int nw = (int)((gridDim.x * (size_t)blockDim.x) >> 5);
    float local = 0.f;
    for (int r = gw; r < 2 * n; r += nw) {
        const float* p; const float* t; int rr;
        if (r < n) { p = p1; t = tx; rr = r; }
        else       { p = p2; t = ty; rr = r - n; }
        float4 pv = *(const float4*)(p + (size_t)rr * 128 + lane * 4);
        float4 tv = *(const float4*)(t + (size_t)rr * 128 + lane * 4);
        float pp = pv.x * pv.x + pv.y * pv.y + pv.z * pv.z + pv.w * pv.w;
        float tt = tv.x * tv.x + tv.y * tv.y + tv.z * tv.z + tv.w * tv.w;
        float pt = pv.x * tv.x + pv.y * tv.y + pv.z * tv.z + pv.w * tv.w;
#pragma unroll
        for (int o = 16; o; o >>= 1) {
            pp += __shfl_xor_sync(0xffffffffu, pp, o);
            tt += __shfl_xor_sync(0xffffffffu, tt, o);
            pt += __shfl_xor_sync(0xffffffffu, pt, o);
        }
        local += 2.f - 2.f * pt * rsqrtf(pp) * rsqrtf(tt);
    }
    __shared__ float red[8];
    int wib = threadIdx.x >> 5;
    if (lane == 0) red[wib] = local;
    __syncthreads();
    if (threadIdx.x == 0) {
        float s = 0.f;
        int nwb = blockDim.x >> 5;
        for (int i = 0; i < nwb; i++) s += red[i];
        atomicAdd(&g_loss, s);
    }
}

__global__ void finish_kernel(float* __restrict__ out, int n, size_t idx) {
    out[idx] = g_loss / (float)n;
}

// ---------------------------------------------------------------------------
extern "C" void kernel_launch(void* const* d_in, const int* in_sizes, int n_in,
                              void* d_out, int out_size) {
    const float* x     = (const float*)d_in[0];
    const float* perb  = (const float*)d_in[1];
    const int*   erow  = (const int*)d_in[2];
    const int*   ecol  = (const int*)d_in[3];
    const float* eval  = (const float*)d_in[4];
    const float* W     = (const float*)d_in[5];
    const float* b     = (const float*)d_in[6];
    const float* Wt    = (const float*)d_in[7];
    const float* bt    = (const float*)d_in[8];
    const float* W1    = (const float*)d_in[9];
    const float* b1    = (const float*)d_in[10];
    const float* gamma = (const float*)d_in[11];
    const float* beta  = (const float*)d_in[12];
    const float* alpha = (const float*)d_in[13];
    const float* W2    = (const float*)d_in[14];
    const float* b2    = (const float*)d_in[15];

    const int n = in_sizes[0] / DD;
    const int E = in_sizes[2];
    float* out = (float*)d_out;

    float* buf = nullptr;
    cudaGetSymbolAddress((void**)&buf, g_buf);
    float* bnp = nullptr;
    cudaGetSymbolAddress((void**)&bnp, g_bnp);

    float* H1  = buf + 0 * NB;   // x1 @ W      -> later U1 = online_x @ W1 + b1
    float* H2  = buf + 1 * NB;   // x2 @ W      -> later U2
    float* HT1 = buf + 2 * NB;   // x1 @ Wt     -> later P1 (predictor out)
    float* HT2 = buf + 3 * NB;   // x2 @ Wt     -> later P2
    float* A1  = buf + 4 * NB;   // online_x  = gcn(x1, W, b)
    float* A2  = buf + 5 * NB;   // enc_x2    = gcn(x2, W, b) = online_y
    float* TY  = buf + 6 * NB;   // target_y  = gcn(x1, Wt, bt)
    float* TX  = buf + 7 * NB;   // target_x  = gcn(x2, Wt, bt)

    const int total = n * DD;
    init_kernel<<<(total + 255) / 256, 256>>>(A1, A2, TY, TX, b, bt, total);

    const int gb = (n + 63) / 64;
    gemm128<0><<<gb, 256>>>(x, nullptr, W,  nullptr, nullptr, nullptr, nullptr, H1,  n);
    gemm128<1><<<gb, 256>>>(x, perb,    W,  nullptr, nullptr, nullptr, nullptr, H2,  n);
    gemm128<0><<<gb, 256>>>(x, nullptr, Wt, nullptr, nullptr, nullptr, nullptr, HT1, n);
    gemm128<1><<<gb, 256>>>(x, perb,    Wt, nullptr, nullptr, nullptr, nullptr, HT2, n);

    dim3 sgrid((unsigned)(((long long)E * 32 + 255) / 256), 4, 1);
    spmm_scatter<<<sgrid, 256>>>(erow, ecol, eval, H1, A1, H2, A2, HT1, TY, HT2, TX, E);

    embed_kernel<<<(total / 4 + 255) / 256, 256>>>(x, perb, A2, out, total / 4);

    // predictor on online_x / online_y
    gemm128<0><<<gb, 256>>>(A1, nullptr, W1, b1, nullptr, nullptr, nullptr, H1, n);  // U1
    gemm128<0><<<gb, 256>>>(A2, nullptr, W1, b1, nullptr, nullptr, nullptr, H2, n);  // U2
    bn_stats<<<(n + 255) / 256, 128>>>(H1, n, 0);
    bn_stats<<<(n + 255) / 256, 128>>>(H2, n, 1);
    bn_finalize<<<1, 256>>>(gamma, n);
    gemm128<2><<<gb, 256>>>(H1, nullptr, W2, b2, bnp,       beta, alpha, HT1, n);    // P1
    gemm128<2><<<gb, 256>>>(H2, nullptr, W2, b2, bnp + 256, beta, alpha, HT2, n);    // P2

    byol_loss<<<2048, 256>>>(HT1, TX, HT2, TY, n);
    finish_kernel<<<1, 1>>>(out, n, (size_t)total);
}

// round 2
// speedup vs baseline: 1.6567x; 1.6567x over previous
#include <cuda_runtime.h>
#include <stdint.h>

#define DD 128
#define NMAX 50000
#define NB ((size_t)NMAX * DD)

// 10 scratch buffers of [NMAX,128] fp32 (static device memory — no allocs)
__device__ __align__(16) float g_buf[10 * NB];
__device__ float g_stats[512];   // [set][{sum,sumsq}][128]
__device__ float g_bnp[512];     // [set][{mu, gamma*rstd}][128]
__device__ float g_loss;

// packed fp32x2 FMA (Blackwell FFMA2)
__device__ __forceinline__ float2 ffma2(float2 a, float2 b, float2 c) {
    union { float2 f; unsigned long long u; } A, B, C, D;
    A.f = a; B.f = b; C.f = c;
    asm("fma.rn.f32x2 %0, %1, %2, %3;" : "=l"(D.u) : "l"(A.u), "l"(B.u), "l"(C.u));
    return D.f;
}

// ---------------------------------------------------------------------------
// init: zero ax/ap aggregation buffers, stats, loss
// ---------------------------------------------------------------------------
__global__ void init_kernel(float* __restrict__ ax, float* __restrict__ ap, int total4) {
    int i = blockIdx.x * blockDim.x + threadIdx.x;
    if (i < 512) g_stats[i] = 0.f;
    if (i == 0) g_loss = 0.f;
    if (i < total4) {
        float4 z = make_float4(0.f, 0.f, 0.f, 0.f);
        ((float4*)ax)[i] = z;
        ((float4*)ap)[i] = z;
    }
}

// ---------------------------------------------------------------------------
// Fused COO SpMM: one warp per edge, aggregates BOTH x and perb.
// ax[r] += v*x[c], ap[r] += v*perb[c] via red.global.add.v4.f32
// ---------------------------------------------------------------------------
__global__ __launch_bounds__(256)
void spmm2(const int* __restrict__ erow, const int* __restrict__ ecol,
           const float* __restrict__ eval,
           const float* __restrict__ x, const float* __restrict__ perb,
           float* __restrict__ ax, float* __restrict__ ap, int E) {
    int w = (int)((blockIdx.x * (size_t)blockDim.x + threadIdx.x) >> 5);
    if (w >= E) return;
    int lane = threadIdx.x & 31;
    int r = __ldg(erow + w);
    int c = __ldg(ecol + w);
    float v = __ldg(eval + w);
    size_t co = (size_t)c * 128 + lane * 4;
    size_t ro = (size_t)r * 128 + lane * 4;
    float4 mx = *(const float4*)(x + co);
    float4 mp = *(const float4*)(perb + co);
    asm volatile("red.global.add.v4.f32 [%0], {%1,%2,%3,%4};"
                 :: "l"(ax + ro), "f"(mx.x * v), "f"(mx.y * v), "f"(mx.z * v), "f"(mx.w * v)
                 : "memory");
    asm volatile("red.global.add.v4.f32 [%0], {%1,%2,%3,%4};"
                 :: "l"(ap + ro), "f"(mp.x * v), "f"(mp.y * v), "f"(mp.z * v), "f"(mp.w * v)
                 : "memory");
}

// ---------------------------------------------------------------------------
// GEMM: out = f(A) @ W + g(...), 128x128 block tile, 8x8 microtile, BK=16,
// FFMA2 inner loop with pre-splatted A in smem. Batched over blockIdx.y (set).
// MODE 0: out = A@W + bias
// MODE 1: out = A@W + add      (+ optional embed = x+perb+out on set 0)
// MODE 2: out = A@W + bias, accumulate per-column sum/sumsq into g_stats[set]
// MODE 3: out = PReLU(BN_set(A))@W + bias
// ---------------------------------------------------------------------------
template <int MODE, bool EMB>
__global__ __launch_bounds__(256, 2)
void gemm2(const float* __restrict__ A0, const float* __restrict__ A1,
           const float* __restrict__ Wm0, const float* __restrict__ Wm1,
           const float* __restrict__ bias0, const float* __restrict__ bias1,
           const float* __restrict__ add0, const float* __restrict__ add1,
           const float* __restrict__ xsrc, const float* __restrict__ psrc,
           float* __restrict__ emb,
           float* __restrict__ out0, float* __restrict__ out1,
           const float* __restrict__ beta, const float* __restrict__ alphap,
           int n) {
    __shared__ float2 As2[128][17];     // [m][k] pre-splatted {v,v}
    __shared__ float  Ws[16][128];      // [k][ncol]
    __shared__ float  s_sum[128], s_sq[128];

    const int tid = threadIdx.x;
    const int set = blockIdx.y;
    const int m0 = blockIdx.x * 128;
    const int tm = tid >> 4;            // 0..15 -> 8 rows
    const int tn = tid & 15;            // 0..15 -> 8 cols

    const float* A    = set ? A1 : A0;
    const float* Wm   = set ? Wm1 : Wm0;
    const float* bias = set ? bias1 : bias0;
    const float* add  = set ? add1 : add0;
    float*       out  = set ? out1 : out0;
    const float* bnp  = g_bnp + set * 256;

    if (MODE == 2 && tid < 128) { s_sum[tid] = 0.f; s_sq[tid] = 0.f; }

    float alpha = 0.f;
    if (MODE == 3) alpha = __ldg(alphap);

    float2 acc[8][4];
#pragma unroll
    for (int i = 0; i < 8; i++)
#pragma unroll
        for (int j = 0; j < 4; j++) acc[i][j] = make_float2(0.f, 0.f);

    for (int k0 = 0; k0 < 128; k0 += 16) {
        // ---- A tile (128 rows x 16 k), splatted store ----
#pragma unroll
        for (int jj = 0; jj < 2; jj++) {
            int f = tid + 256 * jj;      // 0..511
            int row = f >> 2;            // 0..127
            int c4 = f & 3;              // k-chunk of 4
            int gr = m0 + row;
            float4 v = make_float4(0.f, 0.f, 0.f, 0.f);
            if (gr < n) {
                v = *(const float4*)(A + (size_t)gr * 128 + k0 + c4 * 4);
                if (MODE == 3) {
                    int kc = k0 + c4 * 4;
                    float4 mu = *(const float4*)(bnp + kc);
                    float4 gg = *(const float4*)(bnp + 128 + kc);
                    float4 be = *(const float4*)(beta + kc);
                    v.x = fmaf(v.x - mu.x, gg.x, be.x);
                    v.y = fmaf(v.y - mu.y, gg.y, be.y);
                    v.z = fmaf(v.z - mu.z, gg.z, be.z);
                    v.w = fmaf(v.w - mu.w, gg.w, be.w);
                    v.x = v.x >= 0.f ? v.x : alpha * v.x;
                    v.y = v.y >= 0.f ? v.y : alpha * v.y;
                    v.z = v.z >= 0.f ? v.z : alpha * v.z;
                    v.w = v.w >= 0.f ? v.w : alpha * v.w;
                }
            }
            int kb = c4 * 4;
            As2[row][kb + 0] = make_float2(v.x, v.x);
            As2[row][kb + 1] = make_float2(v.y, v.y);
            As2[row][kb + 2] = make_float2(v.z, v.z);
            As2[row][kb + 3] = make_float2(v.w, v.w);
        }
        // ---- W tile (16 k x 128 cols) ----
#pragma unroll
        for (int jj = 0; jj < 2; jj++) {
            int f = tid + 256 * jj;      // 0..511
            int r = f >> 5;              // 0..15
            int c = f & 31;
            *(float4*)&Ws[r][c * 4] = *(const float4*)(Wm + (size_t)(k0 + r) * 128 + c * 4);
        }
        __syncthreads();

#pragma unroll
        for (int kk = 0; kk < 16; kk++) {
            float4 w0v = *(const float4*)&Ws[kk][tn * 8];
            float4 w1v = *(const float4*)&Ws[kk][tn * 8 + 4];
            float2 bp[4];
            bp[0] = make_float2(w0v.x, w0v.y);
            bp[1] = make_float2(w0v.z, w0v.w);
            bp[2] = make_float2(w1v.x, w1v.y);
            bp[3] = make_float2(w1v.z, w1v.w);
#pragma unroll
            for (int i = 0; i < 8; i++) {
                float2 pa = As2[tm * 8 + i][kk];
#pragma unroll
                for (int j = 0; j < 4; j++) acc[i][j] = ffma2(pa, bp[j], acc[i][j]);
            }
        }
        __syncthreads();
    }

    // ---- epilogue ----
    float bb[8];
    if (MODE == 0 || MODE == 2 || MODE == 3) {
        float4 b0v = *(const float4*)(bias + tn * 8);
        float4 b1v = *(const float4*)(bias + tn * 8 + 4);
        bb[0] = b0v.x; bb[1] = b0v.y; bb[2] = b0v.z; bb[3] = b0v.w;
        bb[4] = b1v.x; bb[5] = b1v.y; bb[6] = b1v.z; bb[7] = b1v.w;
    } else {
#pragma unroll
        for (int j = 0; j < 8; j++) bb[j] = 0.f;
    }

    float csum[8], csq[8];
#pragma unroll
    for (int j = 0; j < 8; j++) { csum[j] = 0.f; csq[j] = 0.f; }

#pragma unroll
    for (int i = 0; i < 8; i++) {
        int gr = m0 + tm * 8 + i;
        if (gr >= n) continue;
        float o[8];
        o[0] = acc[i][0].x + bb[0]; o[1] = acc[i][0].y + bb[1];
        o[2] = acc[i][1].x + bb[2]; o[3] = acc[i][1].y + bb[3];
        o[4] = acc[i][2].x + bb[4]; o[5] = acc[i][2].y + bb[5];
        o[6] = acc[i][3].x + bb[6]; o[7] = acc[i][3].y + bb[7];
        size_t off = (size_t)gr * 128 + tn * 8;
        if (MODE == 1) {
            float4 a0v = *(const float4*)(add + off);
            float4 a1v = *(const float4*)(add + off + 4);
            o[0] += a0v.x; o[1] += a0v.y; o[2] += a0v.z; o[3] += a0v.w;
            o[4] += a1v.x; o[5] += a1v.y; o[6] += a1v.z; o[7] += a1v.w;
        }
        float4 s0 = make_float4(o[0], o[1], o[2], o[3]);
        float4 s1 = make_float4(o[4], o[5], o[6], o[7]);
        *(float4*)(out + off) = s0;
        *(float4*)(out + off + 4) = s1;
        if (MODE == 1 && EMB && set == 0) {
            float4 xv0 = *(const float4*)(xsrc + off);
            float4 xv1 = *(const float4*)(xsrc + off + 4);
            float4 pv0 = *(const float4*)(psrc + off);
            float4 pv1 = *(const float4*)(psrc + off + 4);
            float4 e0 = make_float4(s0.x + xv0.x + pv0.x, s0.y + xv0.y + pv0.y,
                                    s0.z + xv0.z + pv0.z, s0.w + xv0.w + pv0.w);
            float4 e1 = make_float4(s1.x + xv1.x + pv1.x, s1.y + xv1.y + pv1.y,
                                    s1.z + xv1.z + pv1.z, s1.w + xv1.w + pv1.w);
            *(float4*)(emb + off) = e0;
            *(float4*)(emb + off + 4) = e1;
        }
        if (MODE == 2) {
#pragma unroll
            for (int j = 0; j < 8; j++) { csum[j] += o[j]; csq[j] += o[j] * o[j]; }
        }
    }

    if (MODE == 2) {
#pragma unroll
        for (int j = 0; j < 8; j++) {
            atomicAdd(&s_sum[tn * 8 + j], csum[j]);
            atomicAdd(&s_sq[tn * 8 + j], csq[j]);
        }
        __syncthreads();
        if (tid < 128) {
            atomicAdd(&g_stats[set * 256 + tid], s_sum[tid]);
            atomicAdd(&g_stats[set * 256 + 128 + tid], s_sq[tid]);
        }
    }
}

// ---------------------------------------------------------------------------
__global__ void bn_finalize(const float* __restrict__ gamma, int n) {
    int t = threadIdx.x;                 // 256 threads: 2 sets x 128 cols
    int set = t >> 7, c = t & 127;
    float s = g_stats[set * 256 + c];
    float q = g_stats[set * 256 + 128 + c];
    float mu = s / (float)n;
    float var = q / (float)n - mu * mu;  // biased (train mode)
    float g = gamma[c] * rsqrtf(var + 1e-5f);
    g_bnp[set * 256 + c] = mu;
    g_bnp[set * 256 + 128 + c] = g;
}

// ---------------------------------------------------------------------------
// BYOL loss: one warp per row, grid-stride over both pairs
// ---------------------------------------------------------------------------
__global__ __launch_bounds__(256)
void byol_loss(const float* __restrict__ p1, const float* __restrict__ tx,
               const float* __restrict__ p2, const float* __restrict__ ty, int n) {
    int gw = (int)((blockIdx.x * (size_t)blockDim.x + threadIdx.x) >> 5);
    int lane = threadIdx.x & 31;
    int nw = (int)((gridDim.x * (size_t)blockDim.x) >> 5);
    float local = 0.f;
    for (int r = gw; r < 2 * n; r += nw) {
        const float* p; const float* t; int rr;
        if (r < n) { p = p1; t = tx; rr = r; }
        else       { p = p2; t = ty; rr = r - n; }
        float4 pv = *(const float4*)(p + (size_t)rr * 128 + lane * 4);
        float4 tv = *(const float4*)(t + (size_t)rr * 128 + lane * 4);
        float pp = pv.x * pv.x + pv.y * pv.y + pv.z * pv.z + pv.w * pv.w;
        float tt = tv.x * tv.x + tv.y * tv.y + tv.z * tv.z + tv.w * tv.w;
        float pt = pv.x * tv.x + pv.y * tv.y + pv.z * tv.z + pv.w * tv.w;
#pragma unroll
        for (int o = 16; o; o >>= 1) {
            pp += __shfl_xor_sync(0xffffffffu, pp, o);
            tt += __shfl_xor_sync(0xffffffffu, tt, o);
            pt += __shfl_xor_sync(0xffffffffu, pt, o);
        }
        local += 2.f - 2.f * pt * rsqrtf(pp) * rsqrtf(tt);
    }
    __shared__ float red[8];
    int wib = threadIdx.x >> 5;
    if (lane == 0) red[wib] = local;
    __syncthreads();
    if (threadIdx.x == 0) {
        float s = 0.f;
        for (int i = 0; i < 8; i++) s += red[i];
        atomicAdd(&g_loss, s);
    }
}

__global__ void finish_kernel(float* __restrict__ out, int n, size_t idx) {
    out[idx] = g_loss / (float)n;
}

// ---------------------------------------------------------------------------
extern "C" void kernel_launch(void* const* d_in, const int* in_sizes, int n_in,
                              void* d_out, int out_size) {
    const float* x     = (const float*)d_in[0];
    const float* perb  = (const float*)d_in[1];
    const int*   erow  = (const int*)d_in[2];
    const int*   ecol  = (const int*)d_in[3];
    const float* eval  = (const float*)d_in[4];
    const float* W     = (const float*)d_in[5];
    const float* b     = (const float*)d_in[6];
    const float* Wt    = (const float*)d_in[7];
    const float* bt    = (const float*)d_in[8];
    const float* W1    = (const float*)d_in[9];
    const float* b1    = (const float*)d_in[10];
    const float* gamma = (const float*)d_in[11];
    const float* beta  = (const float*)d_in[12];
    const float* alpha = (const float*)d_in[13];
    const float* W2    = (const float*)d_in[14];
    const float* b2    = (const float*)d_in[15];

    const int n = in_sizes[0] / DD;
    const int E = in_sizes[2];
    float* out = (float*)d_out;

    float* buf = nullptr;
    cudaGetSymbolAddress((void**)&buf, g_buf);

    float* AX  = buf + 0 * NB;   // adj @ x
    float* AP  = buf + 1 * NB;   // adj @ perb
    float* OX  = buf + 2 * NB;   // online_x = ax@W + b
    float* TY  = buf + 3 * NB;   // target_y = ax@Wt + bt
    float* EX  = buf + 4 * NB;   // enc_x2 = online_y = ap@W + online_x
    float* TX  = buf + 5 * NB;   // target_x = ap@Wt + target_y
    float* U1  = buf + 6 * NB;   // online_x@W1 + b1
    float* U2  = buf + 7 * NB;   // online_y@W1 + b1
    float* P1  = buf + 8 * NB;   // predictor(online_x)
    float* P2  = buf + 9 * NB;   // predictor(online_y)

    const int total = n * DD;
    init_kernel<<<(total / 4 + 255) / 256, 256>>>(AX, AP, total / 4);

    dim3 sgrid((unsigned)(((long long)E * 32 + 255) / 256), 1, 1);
    spmm2<<<sgrid, 256>>>(erow, ecol, eval, x, perb, AX, AP, E);

    dim3 ggrid((n + 127) / 128, 2, 1);
    // online_x = AX@W + b ; target_y = AX@Wt + bt
    gemm2<0, false><<<ggrid, 256>>>(AX, AX, W, Wt, b, bt,
                                    nullptr, nullptr, nullptr, nullptr, nullptr,
                                    OX, TY, nullptr, nullptr, n);
    // enc_x2 = AP@W + online_x (+ embed out) ; target_x = AP@Wt + target_y
    gemm2<1, true><<<ggrid, 256>>>(AP, AP, W, Wt, nullptr, nullptr,
                                   OX, TY, x, perb, out,
                                   EX, TX, nullptr, nullptr, n);
    // U1 = OX@W1 + b1 ; U2 = EX@W1 + b1 ; fused BN stats
    gemm2<2, false><<<ggrid, 256>>>(OX, EX, W1, W1, b1, b1,
                                    nullptr, nullptr, nullptr, nullptr, nullptr,
                                    U1, U2, nullptr, nullptr, n);
    bn_finalize<<<1, 256>>>(gamma, n);
    // P1 = PReLU(BN0(U1))@W2 + b2 ; P2 = PReLU(BN1(U2))@W2 + b2
    gemm2<3, false><<<ggrid, 256>>>(U1, U2, W2, W2, b2, b2,
                                    nullptr, nullptr, nullptr, nullptr, nullptr,
                                    P1, P2, beta, alpha, n);

    byol_loss<<<2048, 256>>>(P1, TX, P2, TY, n);
    finish_kernel<<<1, 1>>>(out, n, (size_t)total);
}

// round 4
// speedup vs baseline: 2.4800x; 1.4970x over previous
#include <cuda_runtime.h>
#include <stdint.h>

#define DD 128
#define NMAX 50000
#define NB ((size_t)NMAX * DD)

// scratch buffers (static device memory — no allocs)
__device__ __align__(16) float g_buf[10 * NB];
__device__ float g_stats[512];   // [set][{sum,sumsq}][128]
__device__ float g_bnp[512];     // [set][{mu, gamma*rstd}][128]
__device__ float g_loss;

__device__ __forceinline__ uint32_t f2tf32(float f) {
    uint32_t u;
    asm("cvt.rna.tf32.f32 %0, %1;" : "=r"(u) : "f"(f));
    return u;
}

__device__ __forceinline__ void mma_tf32(float& d0, float& d1, float& d2, float& d3,
                                         uint32_t a0, uint32_t a1, uint32_t a2, uint32_t a3,
                                         uint32_t b0, uint32_t b1) {
    asm volatile(
        "mma.sync.aligned.m16n8k8.row.col.f32.tf32.tf32.f32 "
        "{%0,%1,%2,%3}, {%4,%5,%6,%7}, {%8,%9}, {%0,%1,%2,%3};"
        : "+f"(d0), "+f"(d1), "+f"(d2), "+f"(d3)
        : "r"(a0), "r"(a1), "r"(a2), "r"(a3), "r"(b0), "r"(b1));
}

// ---------------------------------------------------------------------------
// init: zero ax/ap aggregation buffers, stats, loss
// ---------------------------------------------------------------------------
__global__ void init_kernel(float* __restrict__ ax, float* __restrict__ ap, int total4) {
    int i = blockIdx.x * blockDim.x + threadIdx.x;
    if (i < 512) g_stats[i] = 0.f;
    if (i == 0) g_loss = 0.f;
    if (i < total4) {
        float4 z = make_float4(0.f, 0.f, 0.f, 0.f);
        ((float4*)ax)[i] = z;
        ((float4*)ap)[i] = z;
    }
}

// ---------------------------------------------------------------------------
// Fused COO SpMM: one warp per edge, aggregates BOTH x and perb.
// ---------------------------------------------------------------------------
__global__ __launch_bounds__(256)
void spmm2(const int* __restrict__ erow, const int* __restrict__ ecol,
           const float* __restrict__ eval,
           const float* __restrict__ x, const float* __restrict__ perb,
           float* __restrict__ ax, float* __restrict__ ap, int E) {
    int w = (int)((blockIdx.x * (size_t)blockDim.x + threadIdx.x) >> 5);
    if (w >= E) return;
    int lane = threadIdx.x & 31;
    int r = __ldg(erow + w);
    int c = __ldg(ecol + w);
    float v = __ldg(eval + w);
    size_t co = (size_t)c * 128 + lane * 4;
    size_t ro = (size_t)r * 128 + lane * 4;
    float4 mx = *(const float4*)(x + co);
    float4 mp = *(const float4*)(perb + co);
    asm volatile("red.global.add.v4.f32 [%0], {%1,%2,%3,%4};"
                 :: "l"(ax + ro), "f"(mx.x * v), "f"(mx.y * v), "f"(mx.z * v), "f"(mx.w * v)
                 : "memory");
    asm volatile("red.global.add.v4.f32 [%0], {%1,%2,%3,%4};"
                 :: "l"(ap + ro), "f"(mp.x * v), "f"(mp.y * v), "f"(mp.z * v), "f"(mp.w * v)
                 : "memory");
}

// ---------------------------------------------------------------------------
// tf32 mma.sync GEMM: out = f(A)[n,128] @ W[128,128] + g(...)
// CTA tile 128x128, K=128 in 2 stages of 64. 8 warps = 4(M) x 2(N),
// warp tile 32x64 = 2x8 mma(m16n8k8). blockIdx.y = set.
// MODE 0: out = A@W + bias
// MODE 1: out = A@W + add  (+ embed = out+x+perb on set 0 if EMB)
// MODE 2: out = A@W + bias, fused per-column sum/sumsq into g_stats[set]
// MODE 3: out = PReLU(BN_set(A))@W + bias
// ---------------------------------------------------------------------------
#define APITCH 68
#define BPITCH 136

template <int MODE, bool EMB>
__global__ __launch_bounds__(256, 2)
void tfgemm(const float* __restrict__ A0, const float* __restrict__ A1,
            const float* __restrict__ W0, const float* __restrict__ W1,
            const float* __restrict__ bias0, const float* __restrict__ bias1,
            const float* __restrict__ add0, const float* __restrict__ add1,
            const float* __restrict__ xsrc, const float* __restrict__ psrc,
            float* __restrict__ emb,
            float* __restrict__ out0, float* __restrict__ out1,
            const float* __restrict__ beta, const float* __restrict__ alphap,
            int n) {
    extern __shared__ uint32_t sm[];
    uint32_t* As = sm;                         // [128][APITCH]
    uint32_t* Bs = sm + 128 * APITCH;          // [64][BPITCH]
    float* s_sum = (float*)(sm + 128 * APITCH + 64 * BPITCH);          // [128]
    float* s_sq  = (float*)(sm + 128 * APITCH + 64 * BPITCH + 128);    // [128]

    const int tid = threadIdx.x;
    const int wid = tid >> 5;
    const int lane = tid & 31;
    const int grp = lane >> 2;       // 0..7
    const int tig = lane & 3;        // 0..3
    const int wm = wid & 3;          // M warp: rows wm*32
    const int wn = wid >> 2;         // N warp: cols wn*64
    const int set = blockIdx.y;
    const int m0 = blockIdx.x * 128;

    const float* A    = set ? A1 : A0;
    const float* Wm   = set ? W1 : W0;
    const float* bias = set ? bias1 : bias0;
    const float* add  = set ? add1 : add0;
    float*       out  = set ? out1 : out0;
    const float* bnp  = g_bnp + set * 256;

    if (MODE == 2 && tid < 128) { s_sum[tid] = 0.f; s_sq[tid] = 0.f; }

    float alpha = 0.f;
    if (MODE == 3) alpha = __ldg(alphap);

    float acc[2][8][4];
#pragma unroll
    for (int i = 0; i < 2; i++)
#pragma unroll
        for (int j = 0; j < 8; j++)
#pragma unroll
            for (int q = 0; q < 4; q++) acc[i][j][q] = 0.f;

    for (int st = 0; st < 2; st++) {
        const int kb = st * 64;
        // ---- A stage: 128 rows x 64 k ----
#pragma unroll
        for (int it = 0; it < 8; it++) {
            int idx = tid + it * 256;        // 0..2047 float4 slots
            int row = idx >> 4;              // 0..127
            int c4 = idx & 15;               // 0..15
            int gr = m0 + row;
            float4 v = make_float4(0.f, 0.f, 0.f, 0.f);
            if (gr < n) {
                v = *(const float4*)(A + (size_t)gr * 128 + kb + c4 * 4);
                if (MODE == 3) {
                    int kc = kb + c4 * 4;
                    float4 mu = *(const float4*)(bnp + kc);
                    float4 gg = *(const float4*)(bnp + 128 + kc);
                    float4 be = *(const float4*)(beta + kc);
                    v.x = fmaf(v.x - mu.x, gg.x, be.x);
                    v.y = fmaf(v.y - mu.y, gg.y, be.y);
                    v.z = fmaf(v.z - mu.z, gg.z, be.z);
                    v.w = fmaf(v.w - mu.w, gg.w, be.w);
                    v.x = v.x >= 0.f ? v.x : alpha * v.x;
                    v.y = v.y >= 0.f ? v.y : alpha * v.y;
                    v.z = v.z >= 0.f ? v.z : alpha * v.z;
                    v.w = v.w >= 0.f ? v.w : alpha * v.w;
                }
            }
            uint4 t;
            t.x = f2tf32(v.x); t.y = f2tf32(v.y);
            t.z = f2tf32(v.z); t.w = f2tf32(v.w);
            *(uint4*)(As + row * APITCH + c4 * 4) = t;
        }
        // ---- B stage: 64 k-rows x 128 n ----
#pragma unroll
        for (int it = 0; it < 8; it++) {
            int idx = tid + it * 256;        // 0..2047
            int kr = idx >> 5;               // 0..63
            int c4 = idx & 31;               // 0..31
            float4 v = *(const float4*)(Wm + (size_t)(kb + kr) * 128 + c4 * 4);
            uint4 t;
            t.x = f2tf32(v.x); t.y = f2tf32(v.y);
            t.z = f2tf32(v.z); t.w = f2tf32(v.w);
            *(uint4*)(Bs + kr * BPITCH + c4 * 4) = t;
        }
        __syncthreads();

        // ---- compute: 8 k-steps of 8 ----
#pragma unroll
        for (int ks = 0; ks < 8; ks++) {
            const int k0 = ks * 8;
            uint32_t af[2][4];
#pragma unroll
            for (int mi = 0; mi < 2; mi++) {
                int rb = wm * 32 + mi * 16;
                const uint32_t* ap0 = As + (rb + grp) * APITCH + k0 + tig;
                const uint32_t* ap1 = As + (rb + grp + 8) * APITCH + k0 + tig;
                af[mi][0] = ap0[0];
                af[mi][1] = ap1[0];
                af[mi][2] = ap0[4];
                af[mi][3] = ap1[4];
            }
            uint32_t bf[8][2];
#pragma unroll
            for (int ni = 0; ni < 8; ni++) {
                int nb = wn * 64 + ni * 8;
                bf[ni][0] = Bs[(k0 + tig) * BPITCH + nb + grp];
                bf[ni][1] = Bs[(k0 + tig + 4) * BPITCH + nb + grp];
            }
#pragma unroll
            for (int mi = 0; mi < 2; mi++)
#pragma unroll
                for (int ni = 0; ni < 8; ni++)
                    mma_tf32(acc[mi][ni][0], acc[mi][ni][1], acc[mi][ni][2], acc[mi][ni][3],
                             af[mi][0], af[mi][1], af[mi][2], af[mi][3],
                             bf[ni][0], bf[ni][1]);
        }
        __syncthreads();
    }

    // ---- epilogue ----
    float lsum[8][2], lsq[8][2];
    if (MODE == 2) {
#pragma unroll
        for (int ni = 0; ni < 8; ni++) {
            lsum[ni][0] = 0.f; lsum[ni][1] = 0.f;
            lsq[ni][0] = 0.f; lsq[ni][1] = 0.f;
        }
    }

#pragma unroll
    for (int ni = 0; ni < 8; ni++) {
        int col = wn * 64 + ni * 8 + tig * 2;
        float2 bv = make_float2(0.f, 0.f);
        if (MODE == 0 || MODE == 2 || MODE == 3)
            bv = *(const float2*)(bias + col);
#pragma unroll
        for (int mi = 0; mi < 2; mi++) {
            int r0 = m0 + wm * 32 + mi * 16 + grp;
            int r1 = r0 + 8;
            float c0 = acc[mi][ni][0] + bv.x;
            float c1 = acc[mi][ni][1] + bv.y;
            float c2 = acc[mi][ni][2] + bv.x;
            float c3 = acc[mi][ni][3] + bv.y;
            if (r0 < n) {
                size_t o0 = (size_t)r0 * 128 + col;
                if (MODE == 1) {
                    float2 a = *(const float2*)(add + o0);
                    c0 += a.x; c1 += a.y;
                }
                *(float2*)(out + o0) = make_float2(c0, c1);
                if (MODE == 1 && EMB && set == 0) {
                    float2 xv = *(const float2*)(xsrc + o0);
                    float2 pv = *(const float2*)(psrc + o0);
                    *(float2*)(emb + o0) = make_float2(c0 + xv.x + pv.x, c1 + xv.y + pv.y);
                }
                if (MODE == 2) {
                    lsum[ni][0] += c0; lsum[ni][1] += c1;
                    lsq[ni][0] += c0 * c0; lsq[ni][1] += c1 * c1;
                }
            }
            if (r1 < n) {
                size_t o1 = (size_t)r1 * 128 + col;
                if (MODE == 1) {
                    float2 a = *(const float2*)(add + o1);
                    c2 += a.x; c3 += a.y;
                }
                *(float2*)(out + o1) = make_float2(c2, c3);
                if (MODE == 1 && EMB && set == 0) {
                    float2 xv = *(const float2*)(xsrc + o1);
                    float2 pv = *(const float2*)(psrc + o1);
                    *(float2*)(emb + o1) = make_float2(c2 + xv.x + pv.x, c3 + xv.y + pv.y);
                }
                if (MODE == 2) {
                    lsum[ni][0] += c2; lsum[ni][1] += c3;
                    lsq[ni][0] += c2 * c2; lsq[ni][1] += c3 * c3;
                }
            }
        }
    }

    if (MODE == 2) {
#pragma unroll
        for (int ni = 0; ni < 8; ni++) {
            int col = wn * 64 + ni * 8 + tig * 2;
            atomicAdd(&s_sum[col], lsum[ni][0]);
            atomicAdd(&s_sum[col + 1], lsum[ni][1]);
            atomicAdd(&s_sq[col], lsq[ni][0]);
            atomicAdd(&s_sq[col + 1], lsq[ni][1]);
        }
        __syncthreads();
        if (tid < 128) {
            atomicAdd(&g_stats[set * 256 + tid], s_sum[tid]);
            atomicAdd(&g_stats[set * 256 + 128 + tid], s_sq[tid]);
        }
    }
}

// ---------------------------------------------------------------------------
__global__ void bn_finalize(const float* __restrict__ gamma, int n) {
    int t = threadIdx.x;
    int set = t >> 7, c = t & 127;
    float s = g_stats[set * 256 + c];
    float q = g_stats[set * 256 + 128 + c];
    float mu = s / (float)n;
    float var = q / (float)n - mu * mu;
    float g = gamma[c] * rsqrtf(var + 1e-5f);
    g_bnp[set * 256 + c] = mu;
    g_bnp[set * 256 + 128 + c] = g;
}

// ---------------------------------------------------------------------------
// BYOL loss
// ---------------------------------------------------------------------------
__global__ __launch_bounds__(256)
void byol_loss(const float* __restrict__ p1, const float* __restrict__ tx,
               const float* __restrict__ p2, const float* __restrict__ ty, int n) {
    int gw = (int)((blockIdx.x * (size_t)blockDim.x + threadIdx.x) >> 5);
    int lane = threadIdx.x & 31;
    int nw = (int)((gridDim.x * (size_t)blockDim.x) >> 5);
    float local = 0.f;
    for (int r = gw; r < 2 * n; r += nw) {
        const float* p; const float* t; int rr;
        if (r < n) { p = p1; t = tx; rr = r; }
        else       { p = p2; t = ty; rr = r - n; }
        float4 pv = *(const float4*)(p + (size_t)rr * 128 + lane * 4);
        float4 tv = *(const float4*)(t + (size_t)rr * 128 + lane * 4);
        float pp = pv.x * pv.x + pv.y * pv.y + pv.z * pv.z + pv.w * pv.w;
        float tt = tv.x * tv.x + tv.y * tv.y + tv.z * tv.z + tv.w * tv.w;
        float pt = pv.x * tv.x + pv.y * tv.y + pv.z * tv.z + pv.w * tv.w;
#pragma unroll
        for (int o = 16; o; o >>= 1) {
            pp += __shfl_xor_sync(0xffffffffu, pp, o);
            tt += __shfl_xor_sync(0xffffffffu, tt, o);
            pt += __shfl_xor_sync(0xffffffffu, pt, o);
        }
        local += 2.f - 2.f * pt * rsqrtf(pp) * rsqrtf(tt);
    }
    __shared__ float red[8];
    int wib = threadIdx.x >> 5;
    if (lane == 0) red[wib] = local;
    __syncthreads();
    if (threadIdx.x == 0) {
        float s = 0.f;
        for (int i = 0; i < 8; i++) s += red[i];
        atomicAdd(&g_loss, s);
    }
}

__global__ void finish_kernel(float* __restrict__ out, int n, size_t idx) {
    out[idx] = g_loss / (float)n;
}

// ---------------------------------------------------------------------------
extern "C" void kernel_launch(void* const* d_in, const int* in_sizes, int n_in,
                              void* d_out, int out_size) {
    const float* x     = (const float*)d_in[0];
    const float* perb  = (const float*)d_in[1];
    const int*   erow  = (const int*)d_in[2];
    const int*   ecol  = (const int*)d_in[3];
    const float* eval  = (const float*)d_in[4];
    const float* W     = (const float*)d_in[5];
    const float* b     = (const float*)d_in[6];
    const float* Wt    = (const float*)d_in[7];
    const float* bt    = (const float*)d_in[8];
    const float* W1    = (const float*)d_in[9];
    const float* b1    = (const float*)d_in[10];
    const float* gamma = (const float*)d_in[11];
    const float* beta  = (const float*)d_in[12];
    const float* alpha = (const float*)d_in[13];
    const float* W2    = (const float*)d_in[14];
    const float* b2    = (const float*)d_in[15];

    const int n = in_sizes[0] / DD;
    const int E = in_sizes[2];
    float* out = (float*)d_out;

    float* buf = nullptr;
    cudaGetSymbolAddress((void**)&buf, g_buf);

    float* AX  = buf + 0 * NB;   // adj @ x
    float* AP  = buf + 1 * NB;   // adj @ perb
    float* OX  = buf + 2 * NB;   // online_x = AX@W + b
    float* TY  = buf + 3 * NB;   // target_y = AX@Wt + bt
    float* EX  = buf + 4 * NB;   // enc_x2 = online_y = AP@W + online_x
    float* TX  = buf + 5 * NB;   // target_x = AP@Wt + target_y
    float* U1  = buf + 6 * NB;
    float* U2  = buf + 7 * NB;
    float* P1  = buf + 8 * NB;
    float* P2  = buf + 9 * NB;

    const int SMEM_SZ = (128 * APITCH + 64 * BPITCH + 256) * 4;
    cudaFuncSetAttribute(tfgemm<0, false>, cudaFuncAttributeMaxDynamicSharedMemorySize, SMEM_SZ);
    cudaFuncSetAttribute(tfgemm<1, true>,  cudaFuncAttributeMaxDynamicSharedMemorySize, SMEM_SZ);
    cudaFuncSetAttribute(tfgemm<2, false>, cudaFuncAttributeMaxDynamicSharedMemorySize, SMEM_SZ);
    cudaFuncSetAttribute(tfgemm<3, false>, cudaFuncAttributeMaxDynamicSharedMemorySize, SMEM_SZ);

    const int total = n * DD;
    init_kernel<<<(total / 4 + 255) / 256, 256>>>(AX, AP, total / 4);

    dim3 sgrid((unsigned)(((long long)E * 32 + 255) / 256), 1, 1);
    spmm2<<<sgrid, 256>>>(erow, ecol, eval, x, perb, AX, AP, E);

    dim3 ggrid((n + 127) / 128, 2, 1);
    // online_x = AX@W + b ; target_y = AX@Wt + bt
    tfgemm<0, false><<<ggrid, 256, SMEM_SZ>>>(AX, AX, W, Wt, b, bt,
                                              nullptr, nullptr, nullptr, nullptr, nullptr,
                                              OX, TY, nullptr, nullptr, n);
    // enc_x2 = AP@W + online_x (+embed) ; target_x = AP@Wt + target_y
    tfgemm<1, true><<<ggrid, 256, SMEM_SZ>>>(AP, AP, W, Wt, nullptr, nullptr,
                                             OX, TY, x, perb, out,
                                             EX, TX, nullptr, nullptr, n);
    // U1 = OX@W1 + b1 ; U2 = EX@W1 + b1 ; fused BN stats
    tfgemm<2, false><<<ggrid, 256, SMEM_SZ>>>(OX, EX, W1, W1, b1, b1,
                                              nullptr, nullptr, nullptr, nullptr, nullptr,
                                              U1, U2, nullptr, nullptr, n);
    bn_finalize<<<1, 256>>>(gamma, n);
    // P1 = PReLU(BN0(U1))@W2 + b2 ; P2 = PReLU(BN1(U2))@W2 + b2
    tfgemm<3, false><<<ggrid, 256, SMEM_SZ>>>(U1, U2, W2, W2, b2, b2,
                                              nullptr, nullptr, nullptr, nullptr, nullptr,
                                              P1, P2, beta, alpha, n);

    byol_loss<<<2048, 256>>>(P1, TX, P2, TY, n);
    finish_kernel<<<1, 1>>>(out, n, (size_t)total);
}

// round 5
// speedup vs baseline: 2.5299x; 1.0201x over previous
#include <cuda_runtime.h>
#include <stdint.h>

#define DD 128
#define NMAX 50000
#define NB ((size_t)NMAX * DD)

// scratch buffers (static device memory — no allocs)
__device__ __align__(16) float g_buf[8 * NB];
__device__ float g_stats[512];   // [set][{sum,sumsq}][128]
__device__ float g_bnp[512];     // [set][{mu, gamma*rstd}][128]
__device__ float g_loss;

__device__ __forceinline__ uint32_t f2tf32(float f) {
    uint32_t u;
    asm("cvt.rna.tf32.f32 %0, %1;" : "=r"(u) : "f"(f));
    return u;
}

__device__ __forceinline__ void mma_tf32(float& d0, float& d1, float& d2, float& d3,
                                         uint32_t a0, uint32_t a1, uint32_t a2, uint32_t a3,
                                         uint32_t b0, uint32_t b1) {
    asm volatile(
        "mma.sync.aligned.m16n8k8.row.col.f32.tf32.tf32.f32 "
        "{%0,%1,%2,%3}, {%4,%5,%6,%7}, {%8,%9}, {%0,%1,%2,%3};"
        : "+f"(d0), "+f"(d1), "+f"(d2), "+f"(d3)
        : "r"(a0), "r"(a1), "r"(a2), "r"(a3), "r"(b0), "r"(b1));
}

// ---------------------------------------------------------------------------
// init: zero ax/ap aggregation buffers, stats, loss
// ---------------------------------------------------------------------------
__global__ void init_kernel(float* __restrict__ ax, float* __restrict__ ap, int total4) {
    int i = blockIdx.x * blockDim.x + threadIdx.x;
    if (i < 512) g_stats[i] = 0.f;
    if (i == 0) g_loss = 0.f;
    if (i < total4) {
        float4 z = make_float4(0.f, 0.f, 0.f, 0.f);
        ((float4*)ax)[i] = z;
        ((float4*)ap)[i] = z;
    }
}

// ---------------------------------------------------------------------------
// Fused COO SpMM: one warp per edge, aggregates BOTH x and perb.
// ---------------------------------------------------------------------------
__global__ __launch_bounds__(256)
void spmm2(const int* __restrict__ erow, const int* __restrict__ ecol,
           const float* __restrict__ eval,
           const float* __restrict__ x, const float* __restrict__ perb,
           float* __restrict__ ax, float* __restrict__ ap, int E) {
    int w = (int)((blockIdx.x * (size_t)blockDim.x + threadIdx.x) >> 5);
    if (w >= E) return;
    int lane = threadIdx.x & 31;
    int r = __ldg(erow + w);
    int c = __ldg(ecol + w);
    float v = __ldg(eval + w);
    size_t co = (size_t)c * 128 + lane * 4;
    size_t ro = (size_t)r * 128 + lane * 4;
    float4 mx = *(const float4*)(x + co);
    float4 mp = *(const float4*)(perb + co);
    asm volatile("red.global.add.v4.f32 [%0], {%1,%2,%3,%4};"
                 :: "l"(ax + ro), "f"(mx.x * v), "f"(mx.y * v), "f"(mx.z * v), "f"(mx.w * v)
                 : "memory");
    asm volatile("red.global.add.v4.f32 [%0], {%1,%2,%3,%4};"
                 :: "l"(ap + ro), "f"(mp.x * v), "f"(mp.y * v), "f"(mp.z * v), "f"(mp.w * v)
                 : "memory");
}

// ---------------------------------------------------------------------------
// Unified tf32 mma.sync GEMM. CTA tile 128x128, K=128 in 2 stages of 64.
// 8 warps = 4(M) x 2(N), warp tile 32x64 = 2x8 mma(m16n8k8).
// PHASE 0 (encoder, grid.y=4):
//   set0: OX = AX@W + b          set1: TY = AX@Wt + bt
//   set2: EX = (AX+AP)@W + b, emb = EX + x + perb
//   set3: TX = (AX+AP)@Wt + bt
// PHASE 1 (predictor L1, grid.y=2): U{1,2} = {OX,EX}@W1 + b1, fused BN stats
// PHASE 2 (predictor L2 + loss, grid.y=2): p = PReLU(BN_set(U))@W2 + b2,
//   no store; per-row BYOL loss vs T{X,Y} accumulated into g_loss.
// ---------------------------------------------------------------------------
#define APITCH 68
#define BPITCH 136
#define SMEM_WORDS (128 * APITCH + 64 * BPITCH + 384)

template <int PHASE>
__global__ __launch_bounds__(256, 2)
void fgemm(const float* __restrict__ AX, const float* __restrict__ AP,
           float* __restrict__ OX, float* __restrict__ TY,
           float* __restrict__ EX, float* __restrict__ TX,
           float* __restrict__ U1, float* __restrict__ U2,
           const float* __restrict__ W, const float* __restrict__ Wt,
           const float* __restrict__ b, const float* __restrict__ bt,
           const float* __restrict__ W1, const float* __restrict__ b1,
           const float* __restrict__ W2, const float* __restrict__ b2,
           const float* __restrict__ beta, const float* __restrict__ alphap,
           const float* __restrict__ xsrc, const float* __restrict__ psrc,
           float* __restrict__ emb, int n) {
    extern __shared__ uint32_t sm[];
    uint32_t* As = sm;                           // [128][APITCH]
    uint32_t* Bs = sm + 128 * APITCH;            // [64][BPITCH]
    float* s_r0 = (float*)(sm + 128 * APITCH + 64 * BPITCH);  // [128] sum / pp
    float* s_r1 = s_r0 + 128;                                  // [128] sumsq / tt
    float* s_r2 = s_r1 + 128;                                  // [128] pt

    const int tid = threadIdx.x;
    const int wid = tid >> 5;
    const int lane = tid & 31;
    const int grp = lane >> 2;
    const int tig = lane & 3;
    const int wm = wid & 3;
    const int wn = wid >> 2;
    const int set = blockIdx.y;
    const int m0 = blockIdx.x * 128;

    // per-phase bindings
    const float* A;
    const float* A2 = nullptr;
    const float* Bm;
    const float* bias;
    float* outp = nullptr;
    const float* Tm = nullptr;
    if (PHASE == 0) {
        A = AX;
        if (set >= 2) A2 = AP;
        Bm = (set & 1) ? Wt : W;
        bias = (set & 1) ? bt : b;
        outp = (set == 0) ? OX : (set == 1) ? TY : (set == 2) ? EX : TX;
    } else if (PHASE == 1) {
        A = set ? EX : OX;
        Bm = W1; bias = b1;
        outp = set ? U2 : U1;
    } else {
        A = set ? U2 : U1;
        Bm = W2; bias = b2;
        Tm = set ? TY : TX;
    }
    const float* bnp = g_bnp + set * 256;

    if (PHASE == 1 && tid < 128) { s_r0[tid] = 0.f; s_r1[tid] = 0.f; }
    if (PHASE == 2 && tid < 128) { s_r0[tid] = 0.f; s_r1[tid] = 0.f; s_r2[tid] = 0.f; }

    float alpha = 0.f;
    if (PHASE == 2) alpha = __ldg(alphap);

    float acc[2][8][4];
#pragma unroll
    for (int i = 0; i < 2; i++)
#pragma unroll
        for (int j = 0; j < 8; j++)
#pragma unroll
            for (int q = 0; q < 4; q++) acc[i][j][q] = 0.f;

    for (int st = 0; st < 2; st++) {
        const int kb = st * 64;
        // ---- A stage: 128 rows x 64 k ----
#pragma unroll
        for (int it = 0; it < 8; it++) {
            int idx = tid + it * 256;
            int row = idx >> 4;
            int c4 = idx & 15;
            int gr = m0 + row;
            float4 v = make_float4(0.f, 0.f, 0.f, 0.f);
            if (gr < n) {
                size_t off = (size_t)gr * 128 + kb + c4 * 4;
                v = *(const float4*)(A + off);
                if (PHASE == 0 && A2) {
                    float4 p = *(const float4*)(A2 + off);
                    v.x += p.x; v.y += p.y; v.z += p.z; v.w += p.w;
                }
                if (PHASE == 2) {
                    int kc = kb + c4 * 4;
                    float4 mu = *(const float4*)(bnp + kc);
                    float4 gg = *(const float4*)(bnp + 128 + kc);
                    float4 be = *(const float4*)(beta + kc);
                    v.x = fmaf(v.x - mu.x, gg.x, be.x);
                    v.y = fmaf(v.y - mu.y, gg.y, be.y);
                    v.z = fmaf(v.z - mu.z, gg.z, be.z);
                    v.w = fmaf(v.w - mu.w, gg.w, be.w);
                    v.x = v.x >= 0.f ? v.x : alpha * v.x;
                    v.y = v.y >= 0.f ? v.y : alpha * v.y;
                    v.z = v.z >= 0.f ? v.z : alpha * v.z;
                    v.w = v.w >= 0.f ? v.w : alpha * v.w;
                }
            }
            uint4 t;
            t.x = f2tf32(v.x); t.y = f2tf32(v.y);
            t.z = f2tf32(v.z); t.w = f2tf32(v.w);
            *(uint4*)(As + row * APITCH + c4 * 4) = t;
        }
        // ---- B stage: 64 k-rows x 128 n ----
#pragma unroll
        for (int it = 0; it < 8; it++) {
            int idx = tid + it * 256;
            int kr = idx >> 5;
            int c4 = idx & 31;
            float4 v = *(const float4*)(Bm + (size_t)(kb + kr) * 128 + c4 * 4);
            uint4 t;
            t.x = f2tf32(v.x); t.y = f2tf32(v.y);
            t.z = f2tf32(v.z); t.w = f2tf32(v.w);
            *(uint4*)(Bs + kr * BPITCH + c4 * 4) = t;
        }
        __syncthreads();

        // ---- compute: 8 k-steps of 8 ----
#pragma unroll
        for (int ks = 0; ks < 8; ks++) {
            const int k0 = ks * 8;
            uint32_t af[2][4];
#pragma unroll
            for (int mi = 0; mi < 2; mi++) {
                int rb = wm * 32 + mi * 16;
                const uint32_t* ap0 = As + (rb + grp) * APITCH + k0 + tig;
                const uint32_t* ap1 = As + (rb + grp + 8) * APITCH + k0 + tig;
                af[mi][0] = ap0[0];
                af[mi][1] = ap1[0];
                af[mi][2] = ap0[4];
                af[mi][3] = ap1[4];
            }
            uint32_t bf[8][2];
#pragma unroll
            for (int ni = 0; ni < 8; ni++) {
                int nb = wn * 64 + ni * 8;
                bf[ni][0] = Bs[(k0 + tig) * BPITCH + nb + grp];
                bf[ni][1] = Bs[(k0 + tig + 4) * BPITCH + nb + grp];
            }
#pragma unroll
            for (int mi = 0; mi < 2; mi++)
#pragma unroll
                for (int ni = 0; ni < 8; ni++)
                    mma_tf32(acc[mi][ni][0], acc[mi][ni][1], acc[mi][ni][2], acc[mi][ni][3],
                             af[mi][0], af[mi][1], af[mi][2], af[mi][3],
                             bf[ni][0], bf[ni][1]);
        }
        __syncthreads();
    }

    // =======================================================================
    // Epilogues
    // =======================================================================
    if (PHASE == 2) {
        // ---- fused BYOL loss: no store ----
#pragma unroll
        for (int mi = 0; mi < 2; mi++) {
            int lrA = wm * 32 + mi * 16 + grp;      // local row
            int lrB = lrA + 8;
            int rA = m0 + lrA, rB = m0 + lrB;
            float ppA = 0.f, ttA = 0.f, ptA = 0.f;
            float ppB = 0.f, ttB = 0.f, ptB = 0.f;
#pragma unroll
            for (int ni = 0; ni < 8; ni++) {
                int col = wn * 64 + ni * 8 + tig * 2;
                float2 bv = *(const float2*)(bias + col);
                float c0 = acc[mi][ni][0] + bv.x;
                float c1 = acc[mi][ni][1] + bv.y;
                float c2 = acc[mi][ni][2] + bv.x;
                float c3 = acc[mi][ni][3] + bv.y;
                if (rA < n) {
                    float2 t = *(const float2*)(Tm + (size_t)rA * 128 + col);
                    ppA += c0 * c0 + c1 * c1;
                    ttA += t.x * t.x + t.y * t.y;
                    ptA += c0 * t.x + c1 * t.y;
                }
                if (rB < n) {
                    float2 t = *(const float2*)(Tm + (size_t)rB * 128 + col);
                    ppB += c2 * c2 + c3 * c3;
                    ttB += t.x * t.x + t.y * t.y;
                    ptB += c2 * t.x + c3 * t.y;
                }
            }
            if (rA < n) {
                atomicAdd(&s_r0[lrA], ppA);
                atomicAdd(&s_r1[lrA], ttA);
                atomicAdd(&s_r2[lrA], ptA);
            }
            if (rB < n) {
                atomicAdd(&s_r0[lrB], ppB);
                atomicAdd(&s_r1[lrB], ttB);
                atomicAdd(&s_r2[lrB], ptB);
            }
        }
        __syncthreads();
        if (tid < 128) {
            float l = 0.f;
            if (m0 + tid < n)
                l = 2.f - 2.f * s_r2[tid] * rsqrtf(s_r0[tid]) * rsqrtf(s_r1[tid]);
#pragma unroll
            for (int o = 16; o; o >>= 1) l += __shfl_xor_sync(0xffffffffu, l, o);
            if (lane == 0) s_r0[wid] = l;   // wid 0..3
        }
        __syncthreads();
        if (tid == 0)
            atomicAdd(&g_loss, s_r0[0] + s_r0[1] + s_r0[2] + s_r0[3]);
        return;
    }

    // PHASE 0 / 1: store (+emb, +stats)
    float lsum[8][2], lsq[8][2];
    if (PHASE == 1) {
#pragma unroll
        for (int ni = 0; ni < 8; ni++) {
            lsum[ni][0] = 0.f; lsum[ni][1] = 0.f;
            lsq[ni][0] = 0.f; lsq[ni][1] = 0.f;
        }
    }

    const bool do_emb = (PHASE == 0) && (set == 2);

#pragma unroll
    for (int ni = 0; ni < 8; ni++) {
        int col = wn * 64 + ni * 8 + tig * 2;
        float2 bv = *(const float2*)(bias + col);
#pragma unroll
        for (int mi = 0; mi < 2; mi++) {
            int r0 = m0 + wm * 32 + mi * 16 + grp;
            int r1 = r0 + 8;
            float c0 = acc[mi][ni][0] + bv.x;
            float c1 = acc[mi][ni][1] + bv.y;
            float c2 = acc[mi][ni][2] + bv.x;
            float c3 = acc[mi][ni][3] + bv.y;
            if (r0 < n) {
                size_t o0 = (size_t)r0 * 128 + col;
                *(float2*)(outp + o0) = make_float2(c0, c1);
                if (do_emb) {
                    float2 xv = *(const float2*)(xsrc + o0);
                    float2 pv = *(const float2*)(psrc + o0);
                    *(float2*)(emb + o0) = make_float2(c0 + xv.x + pv.x, c1 + xv.y + pv.y);
                }
                if (PHASE == 1) {
                    lsum[ni][0] += c0; lsum[ni][1] += c1;
                    lsq[ni][0] += c0 * c0; lsq[ni][1] += c1 * c1;
                }
            }
            if (r1 < n) {
                size_t o1 = (size_t)r1 * 128 + col;
                *(float2*)(outp + o1) = make_float2(c2, c3);
                if (do_emb) {
                    float2 xv = *(const float2*)(xsrc + o1);
                    float2 pv = *(const float2*)(psrc + o1);
                    *(float2*)(emb + o1) = make_float2(c2 + xv.x + pv.x, c3 + xv.y + pv.y);
                }
                if (PHASE == 1) {
                    lsum[ni][0] += c2; lsum[ni][1] += c3;
                    lsq[ni][0] += c2 * c2; lsq[ni][1] += c3 * c3;
                }
            }
        }
    }

    if (PHASE == 1) {
#pragma unroll
        for (int ni = 0; ni < 8; ni++) {
            int col = wn * 64 + ni * 8 + tig * 2;
            atomicAdd(&s_r0[col], lsum[ni][0]);
            atomicAdd(&s_r0[col + 1], lsum[ni][1]);
            atomicAdd(&s_r1[col], lsq[ni][0]);
            atomicAdd(&s_r1[col + 1], lsq[ni][1]);
        }
        __syncthreads();
        if (tid < 128) {
            atomicAdd(&g_stats[set * 256 + tid], s_r0[tid]);
            atomicAdd(&g_stats[set * 256 + 128 + tid], s_r1[tid]);
        }
    }
}

// ---------------------------------------------------------------------------
__global__ void bn_finalize(const float* __restrict__ gamma, int n) {
    int t = threadIdx.x;
    int set = t >> 7, c = t & 127;
    float s = g_stats[set * 256 + c];
    float q = g_stats[set * 256 + 128 + c];
    float mu = s / (float)n;
    float var = q / (float)n - mu * mu;
    float g = gamma[c] * rsqrtf(var + 1e-5f);
    g_bnp[set * 256 + c] = mu;
    g_bnp[set * 256 + 128 + c] = g;
}

__global__ void finish_kernel(float* __restrict__ out, int n, size_t idx) {
    out[idx] = g_loss / (float)n;
}

// ---------------------------------------------------------------------------
extern "C" void kernel_launch(void* const* d_in, const int* in_sizes, int n_in,
                              void* d_out, int out_size) {
    const float* x     = (const float*)d_in[0];
    const float* perb  = (const float*)d_in[1];
    const int*   erow  = (const int*)d_in[2];
    const int*   ecol  = (const int*)d_in[3];
    const float* eval  = (const float*)d_in[4];
    const float* W     = (const float*)d_in[5];
    const float* b     = (const float*)d_in[6];
    const float* Wt    = (const float*)d_in[7];
    const float* bt    = (const float*)d_in[8];
    const float* W1    = (const float*)d_in[9];
    const float* b1    = (const float*)d_in[10];
    const float* gamma = (const float*)d_in[11];
    const float* beta  = (const float*)d_in[12];
    const float* alpha = (const float*)d_in[13];
    const float* W2    = (const float*)d_in[14];
    const float* b2    = (const float*)d_in[15];

    const int n = in_sizes[0] / DD;
    const int E = in_sizes[2];
    float* out = (float*)d_out;

    float* buf = nullptr;
    cudaGetSymbolAddress((void**)&buf, g_buf);

    float* AX  = buf + 0 * NB;   // adj @ x
    float* AP  = buf + 1 * NB;   // adj @ perb
    float* OX  = buf + 2 * NB;   // online_x
    float* TY  = buf + 3 * NB;   // target_y
    float* EX  = buf + 4 * NB;   // enc_x2 = online_y
    float* TX  = buf + 5 * NB;   // target_x
    float* U1  = buf + 6 * NB;
    float* U2  = buf + 7 * NB;

    const int SMEM_SZ = SMEM_WORDS * 4;
    cudaFuncSetAttribute(fgemm<0>, cudaFuncAttributeMaxDynamicSharedMemorySize, SMEM_SZ);
    cudaFuncSetAttribute(fgemm<1>, cudaFuncAttributeMaxDynamicSharedMemorySize, SMEM_SZ);
    cudaFuncSetAttribute(fgemm<2>, cudaFuncAttributeMaxDynamicSharedMemorySize, SMEM_SZ);

    const int total = n * DD;
    init_kernel<<<(total / 4 + 255) / 256, 256>>>(AX, AP, total / 4);

    dim3 sgrid((unsigned)(((long long)E * 32 + 255) / 256), 1, 1);
    spmm2<<<sgrid, 256>>>(erow, ecol, eval, x, perb, AX, AP, E);

    const int gbx = (n + 127) / 128;
    dim3 g4(gbx, 4, 1), g2(gbx, 2, 1);

    // encoder: OX, TY, EX(+emb), TX in one launch
    fgemm<0><<<g4, 256, SMEM_SZ>>>(AX, AP, OX, TY, EX, TX, U1, U2,
                                   W, Wt, b, bt, W1, b1, W2, b2,
                                   beta, alpha, x, perb, out, n);
    // predictor L1 + BN stats
    fgemm<1><<<g2, 256, SMEM_SZ>>>(AX, AP, OX, TY, EX, TX, U1, U2,
                                   W, Wt, b, bt, W1, b1, W2, b2,
                                   beta, alpha, x, perb, out, n);
    bn_finalize<<<1, 256>>>(gamma, n);
    // predictor L2 + fused BYOL loss (no stores)
    fgemm<2><<<g2, 256, SMEM_SZ>>>(AX, AP, OX, TY, EX, TX, U1, U2,
                                   W, Wt, b, bt, W1, b1, W2, b2,
                                   beta, alpha, x, perb, out, n);

    finish_kernel<<<1, 1>>>(out, n, (size_t)total);
}

// round 6
// speedup vs baseline: 2.9880x; 1.1811x over previous
#include <cuda_runtime.h>
#include <stdint.h>

#define DD 128
#define NMAX 50000
#define NB ((size_t)NMAX * DD)

// scratch (static device memory — no allocs)
__device__ __align__(16) float g_buf[8 * NB];
__device__ __align__(16) float g_w[4 * DD * DD];   // tf32-rounded W, Wt, W1, W2
__device__ float g_stats[512];   // [set][{sum,sumsq}][128]
__device__ float g_bnp[512];     // [set][{mu, gamma*rstd}][128]
__device__ float g_loss;

__device__ __forceinline__ float rnd_tf32(float f) {
    uint32_t u;
    asm("cvt.rna.tf32.f32 %0, %1;" : "=r"(u) : "f"(f));
    return __uint_as_float(u);
}

__device__ __forceinline__ void mma_tf32(float& d0, float& d1, float& d2, float& d3,
                                         uint32_t a0, uint32_t a1, uint32_t a2, uint32_t a3,
                                         uint32_t b0, uint32_t b1) {
    asm volatile(
        "mma.sync.aligned.m16n8k8.row.col.f32.tf32.tf32.f32 "
        "{%0,%1,%2,%3}, {%4,%5,%6,%7}, {%8,%9}, {%0,%1,%2,%3};"
        : "+f"(d0), "+f"(d1), "+f"(d2), "+f"(d3)
        : "r"(a0), "r"(a1), "r"(a2), "r"(a3), "r"(b0), "r"(b1));
}

__device__ __forceinline__ uint32_t smem_u32(const void* p) {
    uint32_t a;
    asm("{ .reg .u64 t; cvta.to.shared.u64 t, %1; cvt.u32.u64 %0, t; }" : "=r"(a) : "l"(p));
    return a;
}

__device__ __forceinline__ void cp16(uint32_t dst, const void* src, bool pred) {
    int sz = pred ? 16 : 0;
    asm volatile("cp.async.cg.shared.global [%0], [%1], 16, %2;"
                 :: "r"(dst), "l"(src), "r"(sz) : "memory");
}
#define CP_COMMIT() asm volatile("cp.async.commit_group;" ::: "memory")

// ---------------------------------------------------------------------------
// init: zero AX/AP/stats/loss; round weight matrices into g_w
// ---------------------------------------------------------------------------
__global__ void init_kernel(float* __restrict__ ax, float* __restrict__ ap,
                            const float* __restrict__ W, const float* __restrict__ Wt,
                            const float* __restrict__ W1, const float* __restrict__ W2,
                            int total4) {
    int i = blockIdx.x * blockDim.x + threadIdx.x;
    if (i < 512) g_stats[i] = 0.f;
    if (i == 0) g_loss = 0.f;
    if (i < DD * DD) {
        g_w[i]               = rnd_tf32(W[i]);
        g_w[DD * DD + i]     = rnd_tf32(Wt[i]);
        g_w[2 * DD * DD + i] = rnd_tf32(W1[i]);
        g_w[3 * DD * DD + i] = rnd_tf32(W2[i]);
    }
    if (i < total4) {
        float4 z = make_float4(0.f, 0.f, 0.f, 0.f);
        ((float4*)ax)[i] = z;
        ((float4*)ap)[i] = z;
    }
}

// ---------------------------------------------------------------------------
// Fused COO SpMM: one warp per edge, aggregates BOTH x and perb.
// ---------------------------------------------------------------------------
__global__ __launch_bounds__(256)
void spmm2(const int* __restrict__ erow, const int* __restrict__ ecol,
           const float* __restrict__ eval,
           const float* __restrict__ x, const float* __restrict__ perb,
           float* __restrict__ ax, float* __restrict__ ap, int E) {
    int w = (int)((blockIdx.x * (size_t)blockDim.x + threadIdx.x) >> 5);
    if (w >= E) return;
    int lane = threadIdx.x & 31;
    int r = __ldg(erow + w);
    int c = __ldg(ecol + w);
    float v = __ldg(eval + w);
    size_t co = (size_t)c * 128 + lane * 4;
    size_t ro = (size_t)r * 128 + lane * 4;
    float4 mx = *(const float4*)(x + co);
    float4 mp = *(const float4*)(perb + co);
    asm volatile("red.global.add.v4.f32 [%0], {%1,%2,%3,%4};"
                 :: "l"(ax + ro), "f"(mx.x * v), "f"(mx.y * v), "f"(mx.z * v), "f"(mx.w * v)
                 : "memory");
    asm volatile("red.global.add.v4.f32 [%0], {%1,%2,%3,%4};"
                 :: "l"(ap + ro), "f"(mp.x * v), "f"(mp.y * v), "f"(mp.z * v), "f"(mp.w * v)
                 : "memory");
}

// ---------------------------------------------------------------------------
// prep_a: AX <- rnd(AX), AP <- rnd(AX + AP)   (in place, per element)
// ---------------------------------------------------------------------------
__global__ void prep_a(float* __restrict__ ax, float* __restrict__ ap, int total4) {
    int i = blockIdx.x * blockDim.x + threadIdx.x;
    if (i >= total4) return;
    float4 a = ((const float4*)ax)[i];
    float4 p = ((const float4*)ap)[i];
    float4 ra, rs;
    ra.x = rnd_tf32(a.x); ra.y = rnd_tf32(a.y); ra.z = rnd_tf32(a.z); ra.w = rnd_tf32(a.w);
    rs.x = rnd_tf32(a.x + p.x); rs.y = rnd_tf32(a.y + p.y);
    rs.z = rnd_tf32(a.z + p.z); rs.w = rnd_tf32(a.w + p.w);
    ((float4*)ax)[i] = ra;
    ((float4*)ap)[i] = rs;
}

// ---------------------------------------------------------------------------
// bnrelu: U <- rnd(PReLU(BN_set(U)))  in place; grid.y = set
// ---------------------------------------------------------------------------
__global__ void bnrelu(float* __restrict__ U1, float* __restrict__ U2,
                       const float* __restrict__ beta, const float* __restrict__ alphap,
                       int total4) {
    int i = blockIdx.x * blockDim.x + threadIdx.x;
    if (i >= total4) return;
    int set = blockIdx.y;
    float* U = set ? U2 : U1;
    const float* bnp = g_bnp + set * 256;
    float alpha = __ldg(alphap);
    int cb = (i & 31) * 4;
    float4 v = ((const float4*)U)[i];
    float4 mu = *(const float4*)(bnp + cb);
    float4 gg = *(const float4*)(bnp + 128 + cb);
    float4 be = *(const float4*)(beta + cb);
    v.x = fmaf(v.x - mu.x, gg.x, be.x);
    v.y = fmaf(v.y - mu.y, gg.y, be.y);
    v.z = fmaf(v.z - mu.z, gg.z, be.z);
    v.w = fmaf(v.w - mu.w, gg.w, be.w);
    v.x = rnd_tf32(v.x >= 0.f ? v.x : alpha * v.x);
    v.y = rnd_tf32(v.y >= 0.f ? v.y : alpha * v.y);
    v.z = rnd_tf32(v.z >= 0.f ? v.z : alpha * v.z);
    v.w = rnd_tf32(v.w >= 0.f ? v.w : alpha * v.w);
    ((float4*)U)[i] = v;
}

// ---------------------------------------------------------------------------
// Pipelined tf32 GEMM: C[128x128 tile] = A @ B (+bias), cp.async ping-pong,
// BK=32 x 4 chunks. 512 threads = 16 warps (8 M x 2 N), warp tile 16x64.
// PHASE 0 (grid.y=4): set0 OX=AX@W+b (rnd store); set1 TY=AX@Wt+bt;
//                     set2 EX=AS@W+b (rnd store) + emb=EX+x+perb; set3 TX=AS@Wt+bt
// PHASE 1 (grid.y=2): U=A@W1+b1 (full store) + BN stats
// PHASE 2 (grid.y=2): p=V@W2+b2, no store, fused BYOL loss vs T
// ---------------------------------------------------------------------------
#define AP_ 36
#define BP_ 136
#define ACH (128 * AP_)     // words per A chunk
#define BCH (32 * BP_)      // words per B chunk
#define SMEM_BYTES ((2 * ACH + 2 * BCH + 384) * 4)

template <int PHASE>
__global__ __launch_bounds__(512, 2)
void fgemm(const float* __restrict__ AX, const float* __restrict__ AS,
           float* __restrict__ OX, float* __restrict__ TY,
           float* __restrict__ EX, float* __restrict__ TX,
           float* __restrict__ U1, float* __restrict__ U2,
           const float* __restrict__ b, const float* __restrict__ bt,
           const float* __restrict__ b1, const float* __restrict__ b2,
           const float* __restrict__ xsrc, const float* __restrict__ psrc,
           float* __restrict__ emb, int n) {
    extern __shared__ float smf[];
    uint32_t sb = smem_u32(smf);
    float* redf = smf + 2 * ACH + 2 * BCH;

    const int tid = threadIdx.x;
    const int wid = tid >> 5;
    const int lane = tid & 31;
    const int grp = lane >> 2;
    const int tig = lane & 3;
    const int wm = wid >> 1;        // 0..7 -> rows wm*16
    const int wn = wid & 1;         // 0..1 -> cols wn*64
    const int set = blockIdx.y;
    const int m0 = blockIdx.x * 128;

    const float* A;
    const float* Bm;
    const float* bias;
    float* outp = nullptr;
    const float* Tm = nullptr;
    bool rndstore = false, do_emb = false;
    if (PHASE == 0) {
        A = (set >= 2) ? AS : AX;
        Bm = g_w + (set & 1) * DD * DD;
        bias = (set & 1) ? bt : b;
        outp = (set == 0) ? OX : (set == 1) ? TY : (set == 2) ? EX : TX;
        rndstore = !(set & 1);
        do_emb = (set == 2);
    } else if (PHASE == 1) {
        A = set ? EX : OX;
        Bm = g_w + 2 * DD * DD;
        bias = b1;
        outp = set ? U2 : U1;
    } else {
        A = set ? U2 : U1;
        Bm = g_w + 3 * DD * DD;
        bias = b2;
        Tm = set ? TY : TX;
    }

    if (PHASE >= 1 && tid < 384) redf[tid] = 0.f;

    float acc[8][4];
#pragma unroll
    for (int j = 0; j < 8; j++)
#pragma unroll
        for (int q = 0; q < 4; q++) acc[j][q] = 0.f;

    auto issue = [&](int c, int s) {
        const int kb = c * 32;
#pragma unroll
        for (int j = 0; j < 2; j++) {
            int f = tid + j * 512;
            int row = f >> 3, c4 = f & 7;
            uint32_t dst = sb + (uint32_t)((s * ACH + row * AP_ + c4 * 4) * 4);
            cp16(dst, A + (size_t)(m0 + row) * 128 + kb + c4 * 4, (m0 + row) < n);
        }
#pragma unroll
        for (int j = 0; j < 2; j++) {
            int f = tid + j * 512;
            int kr = f >> 5, c4 = f & 31;
            uint32_t dst = sb + (uint32_t)((2 * ACH + s * BCH + kr * BP_ + c4 * 4) * 4);
            cp16(dst, Bm + (size_t)(kb + kr) * 128 + c4 * 4, true);
        }
        CP_COMMIT();
    };

    issue(0, 0);
    for (int c = 0; c < 4; c++) {
        if (c < 3) {
            issue(c + 1, (c + 1) & 1);
            asm volatile("cp.async.wait_group 1;" ::: "memory");
        } else {
            asm volatile("cp.async.wait_group 0;" ::: "memory");
        }
        __syncthreads();
        const uint32_t* Ab = (const uint32_t*)(smf + (c & 1) * ACH);
        const uint32_t* Bb = (const uint32_t*)(smf + 2 * ACH + (c & 1) * BCH);
#pragma unroll
        for (int ks = 0; ks < 4; ks++) {
            const int k0 = ks * 8;
            const uint32_t* a0p = Ab + (wm * 16 + grp) * AP_ + k0 + tig;
            const uint32_t* a1p = a0p + 8 * AP_;
            uint32_t af0 = a0p[0], af1 = a1p[0], af2 = a0p[4], af3 = a1p[4];
#pragma unroll
            for (int ni = 0; ni < 8; ni++) {
                const uint32_t* bp = Bb + (k0 + tig) * BP_ + wn * 64 + ni * 8 + grp;
                uint32_t b0 = bp[0], b1v = bp[4 * BP_];
                mma_tf32(acc[ni][0], acc[ni][1], acc[ni][2], acc[ni][3],
                         af0, af1, af2, af3, b0, b1v);
            }
        }
        __syncthreads();
    }

    // ---- epilogues ----
    const int r0 = m0 + wm * 16 + grp;
    const int r1 = r0 + 8;
    const bool ok0 = r0 < n, ok1 = r1 < n;

    if (PHASE == 2) {
        float pp0 = 0.f, tt0 = 0.f, pt0 = 0.f;
        float pp1 = 0.f, tt1 = 0.f, pt1 = 0.f;
#pragma unroll
        for (int ni = 0; ni < 8; ni++) {
            int col = wn * 64 + ni * 8 + tig * 2;
            float2 bv = *(const float2*)(bias + col);
            float c0 = acc[ni][0] + bv.x, c1 = acc[ni][1] + bv.y;
            float c2 = acc[ni][2] + bv.x, c3 = acc[ni][3] + bv.y;
            if (ok0) {
                float2 t = *(const float2*)(Tm + (size_t)r0 * 128 + col);
                pp0 += c0 * c0 + c1 * c1;
                tt0 += t.x * t.x + t.y * t.y;
                pt0 += c0 * t.x + c1 * t.y;
            }
            if (ok1) {
                float2 t = *(const float2*)(Tm + (size_t)r1 * 128 + col);
                pp1 += c2 * c2 + c3 * c3;
                tt1 += t.x * t.x + t.y * t.y;
                pt1 += c2 * t.x + c3 * t.y;
            }
        }
        // reduce across tig (lane bits 0,1)
#pragma unroll
        for (int msk = 1; msk <= 2; msk <<= 1) {
            pp0 += __shfl_xor_sync(0xffffffffu, pp0, msk);
            tt0 += __shfl_xor_sync(0xffffffffu, tt0, msk);
            pt0 += __shfl_xor_sync(0xffffffffu, pt0, msk);
            pp1 += __shfl_xor_sync(0xffffffffu, pp1, msk);
            tt1 += __shfl_xor_sync(0xffffffffu, tt1, msk);
            pt1 += __shfl_xor_sync(0xffffffffu, pt1, msk);
        }
        if (tig == 0) {
            int lr0 = wm * 16 + grp, lr1 = lr0 + 8;
            atomicAdd(&redf[lr0], pp0);
            atomicAdd(&redf[128 + lr0], tt0);
            atomicAdd(&redf[256 + lr0], pt0);
            atomicAdd(&redf[lr1], pp1);
            atomicAdd(&redf[128 + lr1], tt1);
            atomicAdd(&redf[256 + lr1], pt1);
        }
        __syncthreads();
        if (tid < 128) {
            float l = 0.f;
            if (m0 + tid < n)
                l = 2.f - 2.f * redf[256 + tid] * rsqrtf(redf[tid]) * rsqrtf(redf[128 + tid]);
#pragma unroll
            for (int o = 16; o; o >>= 1) l += __shfl_xor_sync(0xffffffffu, l, o);
            if (lane == 0) redf[320 + wid] = l;
        }
        __syncthreads();
        if (tid == 0)
            atomicAdd(&g_loss, redf[320] + redf[321] + redf[322] + redf[323]);
        return;
    }

#pragma unroll
    for (int ni = 0; ni < 8; ni++) {
        int col = wn * 64 + ni * 8 + tig * 2;
        float2 bv = *(const float2*)(bias + col);
        float c0 = acc[ni][0] + bv.x, c1 = acc[ni][1] + bv.y;
        float c2 = acc[ni][2] + bv.x, c3 = acc[ni][3] + bv.y;
        if (ok0) {
            size_t o0 = (size_t)r0 * 128 + col;
            if (PHASE == 0 && rndstore)
                *(float2*)(outp + o0) = make_float2(rnd_tf32(c0), rnd_tf32(c1));
            else
                *(float2*)(outp + o0) = make_float2(c0, c1);
            if (PHASE == 0 && do_emb) {
                float2 xv = *(const float2*)(xsrc + o0);
                float2 pv = *(const float2*)(psrc + o0);
                *(float2*)(emb + o0) = make_float2(c0 + xv.x + pv.x, c1 + xv.y + pv.y);
            }
        }
        if (ok1) {
            size_t o1 = (size_t)r1 * 128 + col;
            if (PHASE == 0 && rndstore)
                *(float2*)(outp + o1) = make_float2(rnd_tf32(c2), rnd_tf32(c3));
            else
                *(float2*)(outp + o1) = make_float2(c2, c3);
            if (PHASE == 0 && do_emb) {
                float2 xv = *(const float2*)(xsrc + o1);
                float2 pv = *(const float2*)(psrc + o1);
                *(float2*)(emb + o1) = make_float2(c2 + xv.x + pv.x, c3 + xv.y + pv.y);
            }
        }
        if (PHASE == 1) {
            float s0 = (ok0 ? c0 : 0.f) + (ok1 ? c2 : 0.f);
            float s1 = (ok0 ? c1 : 0.f) + (ok1 ? c3 : 0.f);
            float q0 = (ok0 ? c0 * c0 : 0.f) + (ok1 ? c2 * c2 : 0.f);
            float q1 = (ok0 ? c1 * c1 : 0.f) + (ok1 ? c3 * c3 : 0.f);
#pragma unroll
            for (int msk = 4; msk <= 16; msk <<= 1) {
                s0 += __shfl_xor_sync(0xffffffffu, s0, msk);
                s1 += __shfl_xor_sync(0xffffffffu, s1, msk);
                q0 += __shfl_xor_sync(0xffffffffu, q0, msk);
                q1 += __shfl_xor_sync(0xffffffffu, q1, msk);
            }
            if (grp == 0) {
                atomicAdd(&redf[col], s0);
                atomicAdd(&redf[col + 1], s1);
                atomicAdd(&redf[128 + col], q0);
                atomicAdd(&redf[128 + col + 1], q1);
            }
        }
    }

    if (PHASE == 1) {
        __syncthreads();
        if (tid < 256)
            atomicAdd(&g_stats[set * 256 + tid], redf[tid]);
    }
}

// ---------------------------------------------------------------------------
__global__ void bn_finalize(const float* __restrict__ gamma, int n) {
    int t = threadIdx.x;
    int set = t >> 7, c = t & 127;
    float s = g_stats[set * 256 + c];
    float q = g_stats[set * 256 + 128 + c];
    float mu = s / (float)n;
    float var = q / (float)n - mu * mu;
    float g = gamma[c] * rsqrtf(var + 1e-5f);
    g_bnp[set * 256 + c] = mu;
    g_bnp[set * 256 + 128 + c] = g;
}

__global__ void finish_kernel(float* __restrict__ out, int n, size_t idx) {
    out[idx] = g_loss / (float)n;
}

// ---------------------------------------------------------------------------
extern "C" void kernel_launch(void* const* d_in, const int* in_sizes, int n_in,
                              void* d_out, int out_size) {
    const float* x     = (const float*)d_in[0];
    const float* perb  = (const float*)d_in[1];
    const int*   erow  = (const int*)d_in[2];
    const int*   ecol  = (const int*)d_in[3];
    const float* eval  = (const float*)d_in[4];
    const float* W     = (const float*)d_in[5];
    const float* b     = (const float*)d_in[6];
    const float* Wt    = (const float*)d_in[7];
    const float* bt    = (const float*)d_in[8];
    const float* W1    = (const float*)d_in[9];
    const float* b1    = (const float*)d_in[10];
    const float* gamma = (const float*)d_in[11];
    const float* beta  = (const float*)d_in[12];
    const float* alpha = (const float*)d_in[13];
    const float* W2    = (const float*)d_in[14];
    const float* b2    = (const float*)d_in[15];

    const int n = in_sizes[0] / DD;
    const int E = in_sizes[2];
    float* out = (float*)d_out;

    float* buf = nullptr;
    cudaGetSymbolAddress((void**)&buf, g_buf);

    float* AX  = buf + 0 * NB;   // adj@x (tf32-rounded after prep_a)
    float* AS  = buf + 1 * NB;   // adj@x + adj@perb (rounded)
    float* OX  = buf + 2 * NB;   // online_x (rounded)
    float* TY  = buf + 3 * NB;   // target_y (full)
    float* EX  = buf + 4 * NB;   // enc_x2 = online_y (rounded)
    float* TX  = buf + 5 * NB;   // target_x (full)
    float* U1  = buf + 6 * NB;
    float* U2  = buf + 7 * NB;

    cudaFuncSetAttribute(fgemm<0>, cudaFuncAttributeMaxDynamicSharedMemorySize, SMEM_BYTES);
    cudaFuncSetAttribute(fgemm<1>, cudaFuncAttributeMaxDynamicSharedMemorySize, SMEM_BYTES);
    cudaFuncSetAttribute(fgemm<2>, cudaFuncAttributeMaxDynamicSharedMemorySize, SMEM_BYTES);

    const int total = n * DD;
    const int total4 = total / 4;
    init_kernel<<<(total4 + 255) / 256, 256>>>(AX, AS, W, Wt, W1, W2, total4);

    dim3 sgrid((unsigned)(((long long)E * 32 + 255) / 256), 1, 1);
    spmm2<<<sgrid, 256>>>(erow, ecol, eval, x, perb, AX, AS, E);

    prep_a<<<(total4 + 255) / 256, 256>>>(AX, AS, total4);

    const int gbx = (n + 127) / 128;
    dim3 g4(gbx, 4, 1), g2(gbx, 2, 1);

    // encoder: OX, TY, EX(+emb), TX
    fgemm<0><<<g4, 512, SMEM_BYTES>>>(AX, AS, OX, TY, EX, TX, U1, U2,
                                      b, bt, b1, b2, x, perb, out, n);
    // predictor L1 + BN stats
    fgemm<1><<<g2, 512, SMEM_BYTES>>>(AX, AS, OX, TY, EX, TX, U1, U2,
                                      b, bt, b1, b2, x, perb, out, n);
    bn_finalize<<<1, 256>>>(gamma, n);
    dim3 bgrid((total4 + 255) / 256, 2, 1);
    bnrelu<<<bgrid, 256>>>(U1, U2, beta, alpha, total4);
    // predictor L2 + fused BYOL loss
    fgemm<2><<<g2, 512, SMEM_BYTES>>>(AX, AS, OX, TY, EX, TX, U1, U2,
                                      b, bt, b1, b2, x, perb, out, n);

    finish_kernel<<<1, 1>>>(out, n, (size_t)total);
}

// round 7
// speedup vs baseline: 3.0678x; 1.0267x over previous
#include <cuda_runtime.h>
#include <stdint.h>

#define DD 128
#define NMAX 50000
#define NB ((size_t)NMAX * DD)

// scratch (static device memory — no allocs)
__device__ __align__(16) float g_buf[8 * NB];
__device__ __align__(16) float g_w[4 * DD * DD];   // tf32-rounded W, Wt, W1, W2
__device__ float g_stats[512];   // [set][{sum,sumsq}][128]
__device__ float g_bnp[512];     // [set][{mu, gamma*rstd}][128]
__device__ float g_loss;

__device__ __forceinline__ float rnd_tf32(float f) {
    uint32_t u;
    asm("cvt.rna.tf32.f32 %0, %1;" : "=r"(u) : "f"(f));
    return __uint_as_float(u);
}

__device__ __forceinline__ uint32_t rndu(uint32_t u) {
    uint32_t o;
    asm("cvt.rna.tf32.f32 %0, %1;" : "=r"(o) : "f"(__uint_as_float(u)));
    return o;
}

__device__ __forceinline__ uint32_t bnfrag(uint32_t u, float g, float bp, float alpha) {
    float v = __uint_as_float(u);
    v = fmaf(v, g, bp);
    v = fmaxf(v, 0.f) + alpha * fminf(v, 0.f);
    uint32_t o;
    asm("cvt.rna.tf32.f32 %0, %1;" : "=r"(o) : "f"(v));
    return o;
}

__device__ __forceinline__ void mma_tf32(float& d0, float& d1, float& d2, float& d3,
                                         uint32_t a0, uint32_t a1, uint32_t a2, uint32_t a3,
                                         uint32_t b0, uint32_t b1) {
    asm volatile(
        "mma.sync.aligned.m16n8k8.row.col.f32.tf32.tf32.f32 "
        "{%0,%1,%2,%3}, {%4,%5,%6,%7}, {%8,%9}, {%0,%1,%2,%3};"
        : "+f"(d0), "+f"(d1), "+f"(d2), "+f"(d3)
        : "r"(a0), "r"(a1), "r"(a2), "r"(a3), "r"(b0), "r"(b1));
}

__device__ __forceinline__ uint32_t smem_u32(const void* p) {
    uint32_t a;
    asm("{ .reg .u64 t; cvta.to.shared.u64 t, %1; cvt.u32.u64 %0, t; }" : "=r"(a) : "l"(p));
    return a;
}

__device__ __forceinline__ void cp16(uint32_t dst, const void* src, bool pred) {
    int sz = pred ? 16 : 0;
    asm volatile("cp.async.cg.shared.global [%0], [%1], 16, %2;"
                 :: "r"(dst), "l"(src), "r"(sz) : "memory");
}
#define CP_COMMIT() asm volatile("cp.async.commit_group;" ::: "memory")

// ---------------------------------------------------------------------------
// init: zero AX/AS/stats/loss; round weight matrices into g_w
// ---------------------------------------------------------------------------
__global__ void init_kernel(float* __restrict__ ax, float* __restrict__ as,
                            const float* __restrict__ W, const float* __restrict__ Wt,
                            const float* __restrict__ W1, const float* __restrict__ W2,
                            int total4) {
    int i = blockIdx.x * blockDim.x + threadIdx.x;
    if (i < 512) g_stats[i] = 0.f;
    if (i == 0) g_loss = 0.f;
    if (i < DD * DD) {
        g_w[i]               = rnd_tf32(W[i]);
        g_w[DD * DD + i]     = rnd_tf32(Wt[i]);
        g_w[2 * DD * DD + i] = rnd_tf32(W1[i]);
        g_w[3 * DD * DD + i] = rnd_tf32(W2[i]);
    }
    if (i < total4) {
        float4 z = make_float4(0.f, 0.f, 0.f, 0.f);
        ((float4*)ax)[i] = z;
        ((float4*)as)[i] = z;
    }
}

// ---------------------------------------------------------------------------
// Fused COO SpMM: one warp per edge.
// AX[r] += v*x[c];  AS[r] += v*(x[c]+perb[c])   (= adj@x, adj@(x+perb))
// ---------------------------------------------------------------------------
__global__ __launch_bounds__(256)
void spmm2(const int* __restrict__ erow, const int* __restrict__ ecol,
           const float* __restrict__ eval,
           const float* __restrict__ x, const float* __restrict__ perb,
           float* __restrict__ ax, float* __restrict__ as, int E) {
    int w = (int)((blockIdx.x * (size_t)blockDim.x + threadIdx.x) >> 5);
    if (w >= E) return;
    int lane = threadIdx.x & 31;
    int r = __ldg(erow + w);
    int c = __ldg(ecol + w);
    float v = __ldg(eval + w);
    size_t co = (size_t)c * 128 + lane * 4;
    size_t ro = (size_t)r * 128 + lane * 4;
    float4 mx = *(const float4*)(x + co);
    float4 mp = *(const float4*)(perb + co);
    asm volatile("red.global.add.v4.f32 [%0], {%1,%2,%3,%4};"
                 :: "l"(ax + ro), "f"(mx.x * v), "f"(mx.y * v), "f"(mx.z * v), "f"(mx.w * v)
                 : "memory");
    asm volatile("red.global.add.v4.f32 [%0], {%1,%2,%3,%4};"
                 :: "l"(as + ro), "f"((mx.x + mp.x) * v), "f"((mx.y + mp.y) * v),
                    "f"((mx.z + mp.z) * v), "f"((mx.w + mp.w) * v)
                 : "memory");
}

// ---------------------------------------------------------------------------
// Pipelined tf32 GEMM, cp.async ping-pong, BK=32 x 4 chunks.
// 512 threads = 16 warps (8 M x 2 N), warp tile 16x64.
// A raw fp32 in smem; fragments rounded (or BN+PReLU+rounded) in registers.
// grid = (sets, tiles): same-tile CTAs adjacent -> A tiles hit L2.
// PHASE 0 (4 sets): 0: OX=AX@W+b  1: TY=AX@Wt+bt
//                   2: EX=AS@W+b, emb=EX+x+perb   3: TX=AS@Wt+bt
// PHASE 1 (2 sets): U=A@W1+b1 + BN stats
// PHASE 2 (2 sets): p=PReLU(BN(U))@W2+b2 (no store), fused BYOL loss vs T
// ---------------------------------------------------------------------------
#define AP_ 36
#define BP_ 136
#define ACH (128 * AP_)
#define BCH (32 * BP_)
#define RED_OFF (2 * ACH + 2 * BCH)
#define SMEM_BYTES ((RED_OFF + 384 + 256) * 4)

template <int PHASE>
__global__ __launch_bounds__(512, 2)
void fgemm(const float* __restrict__ AX, const float* __restrict__ AS,
           float* __restrict__ OX, float* __restrict__ TY,
           float* __restrict__ EX, float* __restrict__ TX,
           float* __restrict__ U1, float* __restrict__ U2,
           const float* __restrict__ b, const float* __restrict__ bt,
           const float* __restrict__ b1, const float* __restrict__ b2,
           const float* __restrict__ beta, const float* __restrict__ alphap,
           const float* __restrict__ xsrc, const float* __restrict__ psrc,
           float* __restrict__ emb, int n) {
    extern __shared__ float smf[];
    uint32_t sb = smem_u32(smf);
    float* redf = smf + RED_OFF;            // 384 words
    float* sG   = smf + RED_OFF + 384;      // 128
    float* sBp  = sG + 128;                 // 128

    const int tid = threadIdx.x;
    const int wid = tid >> 5;
    const int lane = tid & 31;
    const int grp = lane >> 2;
    const int tig = lane & 3;
    const int wm = wid >> 1;
    const int wn = wid & 1;
    const int set = blockIdx.x;
    const int m0 = blockIdx.y * 128;

    const float* A;
    const float* Bm;
    const float* bias;
    float* outp = nullptr;
    const float* Tm = nullptr;
    bool do_emb = false;
    if (PHASE == 0) {
        A = (set >= 2) ? AS : AX;
        Bm = g_w + (set & 1) * DD * DD;
        bias = (set & 1) ? bt : b;
        outp = (set == 0) ? OX : (set == 1) ? TY : (set == 2) ? EX : TX;
        do_emb = (set == 2);
    } else if (PHASE == 1) {
        A = set ? EX : OX;
        Bm = g_w + 2 * DD * DD;
        bias = b1;
        outp = set ? U2 : U1;
    } else {
        A = set ? U2 : U1;
        Bm = g_w + 3 * DD * DD;
        bias = b2;
        Tm = set ? TY : TX;
    }

    if (PHASE >= 1 && tid < 384) redf[tid] = 0.f;
    float alpha = 0.f;
    if (PHASE == 2) {
        alpha = __ldg(alphap);
        if (tid < 128) {
            float mu = g_bnp[set * 256 + tid];
            float g  = g_bnp[set * 256 + 128 + tid];
            sG[tid] = g;
            sBp[tid] = beta[tid] - mu * g;
        }
    }

    float acc[8][4];
#pragma unroll
    for (int j = 0; j < 8; j++)
#pragma unroll
        for (int q = 0; q < 4; q++) acc[j][q] = 0.f;

    auto issue = [&](int c, int s) {
        const int kb = c * 32;
#pragma unroll
        for (int j = 0; j < 2; j++) {
            int f = tid + j * 512;
            int row = f >> 3, c4 = f & 7;
            uint32_t dst = sb + (uint32_t)((s * ACH + row * AP_ + c4 * 4) * 4);
            cp16(dst, A + (size_t)(m0 + row) * 128 + kb + c4 * 4, (m0 + row) < n);
        }
#pragma unroll
        for (int j = 0; j < 2; j++) {
            int f = tid + j * 512;
            int kr = f >> 5, c4 = f & 31;
            uint32_t dst = sb + (uint32_t)((2 * ACH + s * BCH + kr * BP_ + c4 * 4) * 4);
            cp16(dst, Bm + (size_t)(kb + kr) * 128 + c4 * 4, true);
        }
        CP_COMMIT();
    };

    issue(0, 0);
    for (int c = 0; c < 4; c++) {
        if (c < 3) {
            issue(c + 1, (c + 1) & 1);
            asm volatile("cp.async.wait_group 1;" ::: "memory");
        } else {
            asm volatile("cp.async.wait_group 0;" ::: "memory");
        }
        __syncthreads();
        const uint32_t* Ab = (const uint32_t*)(smf + (c & 1) * ACH);
        const uint32_t* Bb = (const uint32_t*)(smf + 2 * ACH + (c & 1) * BCH);
#pragma unroll
        for (int ks = 0; ks < 4; ks++) {
            const int k0 = ks * 8;
            const uint32_t* a0p = Ab + (wm * 16 + grp) * AP_ + k0 + tig;
            const uint32_t* a1p = a0p + 8 * AP_;
            uint32_t af0 = a0p[0], af1 = a1p[0], af2 = a0p[4], af3 = a1p[4];
            if (PHASE == 2) {
                int kA = c * 32 + k0 + tig;
                float gA = sG[kA], bA = sBp[kA];
                float gB = sG[kA + 4], bB = sBp[kA + 4];
                af0 = bnfrag(af0, gA, bA, alpha);
                af1 = bnfrag(af1, gA, bA, alpha);
                af2 = bnfrag(af2, gB, bB, alpha);
                af3 = bnfrag(af3, gB, bB, alpha);
            } else {
                af0 = rndu(af0); af1 = rndu(af1);
                af2 = rndu(af2); af3 = rndu(af3);
            }
#pragma unroll
            for (int ni = 0; ni < 8; ni++) {
                const uint32_t* bp = Bb + (k0 + tig) * BP_ + wn * 64 + ni * 8 + grp;
                uint32_t b0 = bp[0], b1v = bp[4 * BP_];
                mma_tf32(acc[ni][0], acc[ni][1], acc[ni][2], acc[ni][3],
                         af0, af1, af2, af3, b0, b1v);
            }
        }
        __syncthreads();
    }

    // ---- epilogues ----
    const int r0 = m0 + wm * 16 + grp;
    const int r1 = r0 + 8;
    const bool ok0 = r0 < n, ok1 = r1 < n;

    if (PHASE == 2) {
        float pp0 = 0.f, tt0 = 0.f, pt0 = 0.f;
        float pp1 = 0.f, tt1 = 0.f, pt1 = 0.f;
#pragma unroll
        for (int ni = 0; ni < 8; ni++) {
            int col = wn * 64 + ni * 8 + tig * 2;
            float2 bv = *(const float2*)(bias + col);
            float c0 = acc[ni][0] + bv.x, c1 = acc[ni][1] + bv.y;
            float c2 = acc[ni][2] + bv.x, c3 = acc[ni][3] + bv.y;
            if (ok0) {
                float2 t = *(const float2*)(Tm + (size_t)r0 * 128 + col);
                pp0 += c0 * c0 + c1 * c1;
                tt0 += t.x * t.x + t.y * t.y;
                pt0 += c0 * t.x + c1 * t.y;
            }
            if (ok1) {
                float2 t = *(const float2*)(Tm + (size_t)r1 * 128 + col);
                pp1 += c2 * c2 + c3 * c3;
                tt1 += t.x * t.x + t.y * t.y;
                pt1 += c2 * t.x + c3 * t.y;
            }
        }
#pragma unroll
        for (int msk = 1; msk <= 2; msk <<= 1) {
            pp0 += __shfl_xor_sync(0xffffffffu, pp0, msk);
            tt0 += __shfl_xor_sync(0xffffffffu, tt0, msk);
            pt0 += __shfl_xor_sync(0xffffffffu, pt0, msk);
            pp1 += __shfl_xor_sync(0xffffffffu, pp1, msk);
            tt1 += __shfl_xor_sync(0xffffffffu, tt1, msk);
            pt1 += __shfl_xor_sync(0xffffffffu, pt1, msk);
        }
        if (tig == 0) {
            int lr0 = wm * 16 + grp, lr1 = lr0 + 8;
            atomicAdd(&redf[lr0], pp0);
            atomicAdd(&redf[128 + lr0], tt0);
            atomicAdd(&redf[256 + lr0], pt0);
            atomicAdd(&redf[lr1], pp1);
            atomicAdd(&redf[128 + lr1], tt1);
            atomicAdd(&redf[256 + lr1], pt1);
        }
        __syncthreads();
        if (tid < 128) {
            float l = 0.f;
            if (m0 + tid < n)
                l = 2.f - 2.f * redf[256 + tid] * rsqrtf(redf[tid]) * rsqrtf(redf[128 + tid]);
#pragma unroll
            for (int o = 16; o; o >>= 1) l += __shfl_xor_sync(0xffffffffu, l, o);
            if (lane == 0) redf[320 + wid] = l;
        }
        __syncthreads();
        if (tid == 0)
            atomicAdd(&g_loss, redf[320] + redf[321] + redf[322] + redf[323]);
        return;
    }

#pragma unroll
    for (int ni = 0; ni < 8; ni++) {
        int col = wn * 64 + ni * 8 + tig * 2;
        float2 bv = *(const float2*)(bias + col);
        float c0 = acc[ni][0] + bv.x, c1 = acc[ni][1] + bv.y;
        float c2 = acc[ni][2] + bv.x, c3 = acc[ni][3] + bv.y;
        if (ok0) {
            size_t o0 = (size_t)r0 * 128 + col;
            *(float2*)(outp + o0) = make_float2(c0, c1);
            if (PHASE == 0 && do_emb) {
                float2 xv = *(const float2*)(xsrc + o0);
                float2 pv = *(const float2*)(psrc + o0);
                *(float2*)(emb + o0) = make_float2(c0 + xv.x + pv.x, c1 + xv.y + pv.y);
            }
        }
        if (ok1) {
            size_t o1 = (size_t)r1 * 128 + col;
            *(float2*)(outp + o1) = make_float2(c2, c3);
            if (PHASE == 0 && do_emb) {
                float2 xv = *(const float2*)(xsrc + o1);
                float2 pv = *(const float2*)(psrc + o1);
                *(float2*)(emb + o1) = make_float2(c2 + xv.x + pv.x, c3 + xv.y + pv.y);
            }
        }
        if (PHASE == 1) {
            float s0 = (ok0 ? c0 : 0.f) + (ok1 ? c2 : 0.f);
            float s1 = (ok0 ? c1 : 0.f) + (ok1 ? c3 : 0.f);
            float q0 = (ok0 ? c0 * c0 : 0.f) + (ok1 ? c2 * c2 : 0.f);
            float q1 = (ok0 ? c1 * c1 : 0.f) + (ok1 ? c3 * c3 : 0.f);
#pragma unroll
            for (int msk = 4; msk <= 16; msk <<= 1) {
                s0 += __shfl_xor_sync(0xffffffffu, s0, msk);
                s1 += __shfl_xor_sync(0xffffffffu, s1, msk);
                q0 += __shfl_xor_sync(0xffffffffu, q0, msk);
                q1 += __shfl_xor_sync(0xffffffffu, q1, msk);
            }
            if (grp == 0) {
                atomicAdd(&redf[col], s0);
                atomicAdd(&redf[col + 1], s1);
                atomicAdd(&redf[128 + col], q0);
                atomicAdd(&redf[128 + col + 1], q1);
            }
        }
    }

    if (PHASE == 1) {
        __syncthreads();
        if (tid < 256)
            atomicAdd(&g_stats[set * 256 + tid], redf[tid]);
    }
}

// ---------------------------------------------------------------------------
__global__ void bn_finalize(const float* __restrict__ gamma, int n) {
    int t = threadIdx.x;
    int set = t >> 7, c = t & 127;
    float s = g_stats[set * 256 + c];
    float q = g_stats[set * 256 + 128 + c];
    float mu = s / (float)n;
    float var = q / (float)n - mu * mu;
    float g = gamma[c] * rsqrtf(var + 1e-5f);
    g_bnp[set * 256 + c] = mu;
    g_bnp[set * 256 + 128 + c] = g;
}

__global__ void finish_kernel(float* __restrict__ out, int n, size_t idx) {
    out[idx] = g_loss / (float)n;
}

// ---------------------------------------------------------------------------
extern "C" void kernel_launch(void* const* d_in, const int* in_sizes, int n_in,
                              void* d_out, int out_size) {
    const float* x     = (const float*)d_in[0];
    const float* perb  = (const float*)d_in[1];
    const int*   erow  = (const int*)d_in[2];
    const int*   ecol  = (const int*)d_in[3];
    const float* eval  = (const float*)d_in[4];
    const float* W     = (const float*)d_in[5];
    const float* b     = (const float*)d_in[6];
    const float* Wt    = (const float*)d_in[7];
    const float* bt    = (const float*)d_in[8];
    const float* W1    = (const float*)d_in[9];
    const float* b1    = (const float*)d_in[10];
    const float* gamma = (const float*)d_in[11];
    const float* beta  = (const float*)d_in[12];
    const float* alpha = (const float*)d_in[13];
    const float* W2    = (const float*)d_in[14];
    const float* b2    = (const float*)d_in[15];

    const int n = in_sizes[0] / DD;
    const int E = in_sizes[2];
    float* out = (float*)d_out;

    float* buf = nullptr;
    cudaGetSymbolAddress((void**)&buf, g_buf);

    float* AX  = buf + 0 * NB;   // adj@x
    float* AS  = buf + 1 * NB;   // adj@(x+perb)
    float* OX  = buf + 2 * NB;   // online_x
    float* TY  = buf + 3 * NB;   // target_y
    float* EX  = buf + 4 * NB;   // enc_x2 = online_y
    float* TX  = buf + 5 * NB;   // target_x
    float* U1  = buf + 6 * NB;
    float* U2  = buf + 7 * NB;

    cudaFuncSetAttribute(fgemm<0>, cudaFuncAttributeMaxDynamicSharedMemorySize, SMEM_BYTES);
    cudaFuncSetAttribute(fgemm<1>, cudaFuncAttributeMaxDynamicSharedMemorySize, SMEM_BYTES);
    cudaFuncSetAttribute(fgemm<2>, cudaFuncAttributeMaxDynamicSharedMemorySize, SMEM_BYTES);

    const int total = n * DD;
    const int total4 = total / 4;
    init_kernel<<<(total4 + 255) / 256, 256>>>(AX, AS, W, Wt, W1, W2, total4);

    dim3 sgrid((unsigned)(((long long)E * 32 + 255) / 256), 1, 1);
    spmm2<<<sgrid, 256>>>(erow, ecol, eval, x, perb, AX, AS, E);

    const int gbx = (n + 127) / 128;
    dim3 g4(4, gbx, 1), g2(2, gbx, 1);

    // encoder: OX, TY, EX(+emb), TX
    fgemm<0><<<g4, 512, SMEM_BYTES>>>(AX, AS, OX, TY, EX, TX, U1, U2,
                                      b, bt, b1, b2, beta, alpha, x, perb, out, n);
    // predictor L1 + BN stats
    fgemm<1><<<g2, 512, SMEM_BYTES>>>(AX, AS, OX, TY, EX, TX, U1, U2,
                                      b, bt, b1, b2, beta, alpha, x, perb, out, n);
    bn_finalize<<<1, 256>>>(gamma, n);
    // predictor L2 (fused BN+PReLU on A-fragments) + fused BYOL loss
    fgemm<2><<<g2, 512, SMEM_BYTES>>>(AX, AS, OX, TY, EX, TX, U1, U2,
                                      b, bt, b1, b2, beta, alpha, x, perb, out, n);

    finish_kernel<<<1, 1>>>(out, n, (size_t)total);
}

// round 8
// speedup vs baseline: 3.0851x; 1.0057x over previous
#include <cuda_runtime.h>
#include <stdint.h>

#define DD 128
#define NMAX 50000
#define EMAX 800000
#define NB ((size_t)NMAX * DD)

// scratch (static device memory — no allocs)
__device__ __align__(16) float g_buf[8 * NB];
__device__ __align__(16) float g_w[4 * DD * DD];   // tf32-rounded W, Wt, W1, W2
__device__ float g_stats[512];   // [set][{sum,sumsq}][128]
__device__ float g_bnp[512];     // [set][{mu, gamma*rstd}][128]
__device__ float g_loss;
// CSR build
__device__ int   g_cnt[NMAX + 1];
__device__ int   g_cursor[NMAX];
__device__ int   g_cols[EMAX];
__device__ float g_vals[EMAX];

__device__ __forceinline__ float rnd_tf32(float f) {
    uint32_t u;
    asm("cvt.rna.tf32.f32 %0, %1;" : "=r"(u) : "f"(f));
    return __uint_as_float(u);
}

__device__ __forceinline__ uint32_t rndu(uint32_t u) {
    uint32_t o;
    asm("cvt.rna.tf32.f32 %0, %1;" : "=r"(o) : "f"(__uint_as_float(u)));
    return o;
}

__device__ __forceinline__ uint32_t bnfrag(uint32_t u, float g, float bp, float alpha) {
    float v = __uint_as_float(u);
    v = fmaf(v, g, bp);
    v = fmaxf(v, 0.f) + alpha * fminf(v, 0.f);
    uint32_t o;
    asm("cvt.rna.tf32.f32 %0, %1;" : "=r"(o) : "f"(v));
    return o;
}

__device__ __forceinline__ void mma_tf32(float& d0, float& d1, float& d2, float& d3,
                                         uint32_t a0, uint32_t a1, uint32_t a2, uint32_t a3,
                                         uint32_t b0, uint32_t b1) {
    asm volatile(
        "mma.sync.aligned.m16n8k8.row.col.f32.tf32.tf32.f32 "
        "{%0,%1,%2,%3}, {%4,%5,%6,%7}, {%8,%9}, {%0,%1,%2,%3};"
        : "+f"(d0), "+f"(d1), "+f"(d2), "+f"(d3)
        : "r"(a0), "r"(a1), "r"(a2), "r"(a3), "r"(b0), "r"(b1));
}

__device__ __forceinline__ uint32_t smem_u32(const void* p) {
    uint32_t a;
    asm("{ .reg .u64 t; cvta.to.shared.u64 t, %1; cvt.u32.u64 %0, t; }" : "=r"(a) : "l"(p));
    return a;
}

__device__ __forceinline__ void cp16(uint32_t dst, const void* src, bool pred) {
    int sz = pred ? 16 : 0;
    asm volatile("cp.async.cg.shared.global [%0], [%1], 16, %2;"
                 :: "r"(dst), "l"(src), "r"(sz) : "memory");
}
#define CP_COMMIT() asm volatile("cp.async.commit_group;" ::: "memory")

// ---------------------------------------------------------------------------
// init: zero hist/stats/loss; round weight matrices into g_w
// ---------------------------------------------------------------------------
__global__ void init_kernel(const float* __restrict__ W, const float* __restrict__ Wt,
                            const float* __restrict__ W1, const float* __restrict__ W2,
                            int n) {
    int i = blockIdx.x * blockDim.x + threadIdx.x;
    if (i < 512) g_stats[i] = 0.f;
    if (i == 0) g_loss = 0.f;
    if (i <= n) g_cnt[i] = 0;
    if (i < DD * DD) {
        g_w[i]               = rnd_tf32(W[i]);
        g_w[DD * DD + i]     = rnd_tf32(Wt[i]);
        g_w[2 * DD * DD + i] = rnd_tf32(W1[i]);
        g_w[3 * DD * DD + i] = rnd_tf32(W2[i]);
    }
}

// ---------------------------------------------------------------------------
// CSR build: histogram -> scan -> scatter
// ---------------------------------------------------------------------------
__global__ void hist_kernel(const int* __restrict__ erow, int E) {
    int i = blockIdx.x * blockDim.x + threadIdx.x;
    if (i < E) atomicAdd(&g_cnt[erow[i] + 1], 1);
}

__global__ __launch_bounds__(1024)
void scan_kernel(int n) {
    const int n1 = n + 1;
    const int t = threadIdx.x;
    const int chunk = (n1 + 1023) / 1024;
    const int lo = t * chunk;
    const int hi = min(lo + chunk, n1);
    int s = 0;
    for (int i = lo; i < hi; i++) s += g_cnt[i];
    __shared__ int sm[1024];
    sm[t] = s;
    __syncthreads();
    for (int off = 1; off < 1024; off <<= 1) {
        int v = (t >= off) ? sm[t - off] : 0;
        __syncthreads();
        sm[t] += v;
        __syncthreads();
    }
    int run = sm[t] - s;   // exclusive prefix of this chunk
    for (int i = lo; i < hi; i++) {
        run += g_cnt[i];
        g_cnt[i] = run;              // inclusive scan: start offset of row i
        if (i < n) g_cursor[i] = run;
    }
}

__global__ void scatter_kernel(const int* __restrict__ erow, const int* __restrict__ ecol,
                               const float* __restrict__ eval, int E) {
    int i = blockIdx.x * blockDim.x + threadIdx.x;
    if (i >= E) return;
    int r = erow[i];
    int pos = atomicAdd(&g_cursor[r], 1);
    g_cols[pos] = ecol[i];
    g_vals[pos] = eval[i];
}

// ---------------------------------------------------------------------------
// CSR SpMM: one warp per row, gather-only, no atomics.
// AX[r] = sum v*x[c];  AS[r] = sum v*(x[c]+perb[c])
// ---------------------------------------------------------------------------
__global__ __launch_bounds__(256)
void spmm_csr(const float* __restrict__ x, const float* __restrict__ perb,
              float* __restrict__ ax, float* __restrict__ as, int n) {
    int r = (int)((blockIdx.x * (size_t)blockDim.x + threadIdx.x) >> 5);
    if (r >= n) return;
    int lane = threadIdx.x & 31;
    int base = g_cnt[r], end = g_cnt[r + 1];
    float4 a0 = make_float4(0.f, 0.f, 0.f, 0.f);
    float4 a1 = make_float4(0.f, 0.f, 0.f, 0.f);
    for (int e0 = base; e0 < end; e0 += 32) {
        int ee = e0 + lane;
        int c = 0; float v = 0.f;
        if (ee < end) { c = g_cols[ee]; v = g_vals[ee]; }
        int cnt = min(32, end - e0);
        for (int j = 0; j < cnt; j++) {
            int cc = __shfl_sync(0xffffffffu, c, j);
            float vv = __shfl_sync(0xffffffffu, v, j);
            size_t co = (size_t)cc * 128 + lane * 4;
            float4 xv = *(const float4*)(x + co);
            float4 pv = *(const float4*)(perb + co);
            a0.x += vv * xv.x; a0.y += vv * xv.y;
            a0.z += vv * xv.z; a0.w += vv * xv.w;
            a1.x += vv * (xv.x + pv.x); a1.y += vv * (xv.y + pv.y);
            a1.z += vv * (xv.z + pv.z); a1.w += vv * (xv.w + pv.w);
        }
    }
    size_t ro = (size_t)r * 128 + lane * 4;
    *(float4*)(ax + ro) = a0;
    *(float4*)(as + ro) = a1;
}

// ---------------------------------------------------------------------------
// Pipelined tf32 GEMM (unchanged from R7)
// ---------------------------------------------------------------------------
#define AP_ 36
#define BP_ 136
#define ACH (128 * AP_)
#define BCH (32 * BP_)
#define RED_OFF (2 * ACH + 2 * BCH)
#define SMEM_BYTES ((RED_OFF + 384 + 256) * 4)

template <int PHASE>
__global__ __launch_bounds__(512, 2)
void fgemm(const float* __restrict__ AX, const float* __restrict__ AS,
           float* __restrict__ OX, float* __restrict__ TY,
           float* __restrict__ EX, float* __restrict__ TX,
           float* __restrict__ U1, float* __restrict__ U2,
           const float* __restrict__ b, const float* __restrict__ bt,
           const float* __restrict__ b1, const float* __restrict__ b2,
           const float* __restrict__ beta, const float* __restrict__ alphap,
           const float* __restrict__ xsrc, const float* __restrict__ psrc,
           float* __restrict__ emb, int n) {
    extern __shared__ float smf[];
    uint32_t sb = smem_u32(smf);
    float* redf = smf + RED_OFF;
    float* sG   = smf + RED_OFF + 384;
    float* sBp  = sG + 128;

    const int tid = threadIdx.x;
    const int wid = tid >> 5;
    const int lane = tid & 31;
    const int grp = lane >> 2;
    const int tig = lane & 3;
    const int wm = wid >> 1;
    const int wn = wid & 1;
    const int set = blockIdx.x;
    const int m0 = blockIdx.y * 128;

    const float* A;
    const float* Bm;
    const float* bias;
    float* outp = nullptr;
    const float* Tm = nullptr;
    bool do_emb = false;
    if (PHASE == 0) {
        A = (set >= 2) ? AS : AX;
        Bm = g_w + (set & 1) * DD * DD;
        bias = (set & 1) ? bt : b;
        outp = (set == 0) ? OX : (set == 1) ? TY : (set == 2) ? EX : TX;
        do_emb = (set == 2);
    } else if (PHASE == 1) {
        A = set ? EX : OX;
        Bm = g_w + 2 * DD * DD;
        bias = b1;
        outp = set ? U2 : U1;
    } else {
        A = set ? U2 : U1;
        Bm = g_w + 3 * DD * DD;
        bias = b2;
        Tm = set ? TY : TX;
    }

    if (PHASE >= 1 && tid < 384) redf[tid] = 0.f;
    float alpha = 0.f;
    if (PHASE == 2) {
        alpha = __ldg(alphap);
        if (tid < 128) {
            float mu = g_bnp[set * 256 + tid];
            float g  = g_bnp[set * 256 + 128 + tid];
            sG[tid] = g;
            sBp[tid] = beta[tid] - mu * g;
        }
    }

    float acc[8][4];
#pragma unroll
    for (int j = 0; j < 8; j++)
#pragma unroll
        for (int q = 0; q < 4; q++) acc[j][q] = 0.f;

    auto issue = [&](int c, int s) {
        const int kb = c * 32;
#pragma unroll
        for (int j = 0; j < 2; j++) {
            int f = tid + j * 512;
            int row = f >> 3, c4 = f & 7;
            uint32_t dst = sb + (uint32_t)((s * ACH + row * AP_ + c4 * 4) * 4);
            cp16(dst, A + (size_t)(m0 + row) * 128 + kb + c4 * 4, (m0 + row) < n);
        }
#pragma unroll
        for (int j = 0; j < 2; j++) {
            int f = tid + j * 512;
            int kr = f >> 5, c4 = f & 31;
            uint32_t dst = sb + (uint32_t)((2 * ACH + s * BCH + kr * BP_ + c4 * 4) * 4);
            cp16(dst, Bm + (size_t)(kb + kr) * 128 + c4 * 4, true);
        }
        CP_COMMIT();
    };

    issue(0, 0);
    for (int c = 0; c < 4; c++) {
        if (c < 3) {
            issue(c + 1, (c + 1) & 1);
            asm volatile("cp.async.wait_group 1;" ::: "memory");
        } else {
            asm volatile("cp.async.wait_group 0;" ::: "memory");
        }
        __syncthreads();
        const uint32_t* Ab = (const uint32_t*)(smf + (c & 1) * ACH);
        const uint32_t* Bb = (const uint32_t*)(smf + 2 * ACH + (c & 1) * BCH);
#pragma unroll
        for (int ks = 0; ks < 4; ks++) {
            const int k0 = ks * 8;
            const uint32_t* a0p = Ab + (wm * 16 + grp) * AP_ + k0 + tig;
            const uint32_t* a1p = a0p + 8 * AP_;
            uint32_t af0 = a0p[0], af1 = a1p[0], af2 = a0p[4], af3 = a1p[4];
            if (PHASE == 2) {
                int kA = c * 32 + k0 + tig;
                float gA = sG[kA], bA = sBp[kA];
                float gB = sG[kA + 4], bB = sBp[kA + 4];
                af0 = bnfrag(af0, gA, bA, alpha);
                af1 = bnfrag(af1, gA, bA, alpha);
                af2 = bnfrag(af2, gB, bB, alpha);
                af3 = bnfrag(af3, gB, bB, alpha);
            } else {
                af0 = rndu(af0); af1 = rndu(af1);
                af2 = rndu(af2); af3 = rndu(af3);
            }
#pragma unroll
            for (int ni = 0; ni < 8; ni++) {
                const uint32_t* bp = Bb + (k0 + tig) * BP_ + wn * 64 + ni * 8 + grp;
                uint32_t b0 = bp[0], b1v = bp[4 * BP_];
                mma_tf32(acc[ni][0], acc[ni][1], acc[ni][2], acc[ni][3],
                         af0, af1, af2, af3, b0, b1v);
            }
        }
        __syncthreads();
    }

    const int r0 = m0 + wm * 16 + grp;
    const int r1 = r0 + 8;
    const bool ok0 = r0 < n, ok1 = r1 < n;

    if (PHASE == 2) {
        float pp0 = 0.f, tt0 = 0.f, pt0 = 0.f;
        float pp1 = 0.f, tt1 = 0.f, pt1 = 0.f;
#pragma unroll
        for (int ni = 0; ni < 8; ni++) {
            int col = wn * 64 + ni * 8 + tig * 2;
            float2 bv = *(const float2*)(bias + col);
            float c0 = acc[ni][0] + bv.x, c1 = acc[ni][1] + bv.y;
            float c2 = acc[ni][2] + bv.x, c3 = acc[ni][3] + bv.y;
            if (ok0) {
                float2 t = *(const float2*)(Tm + (size_t)r0 * 128 + col);
                pp0 += c0 * c0 + c1 * c1;
                tt0 += t.x * t.x + t.y * t.y;
                pt0 += c0 * t.x + c1 * t.y;
            }
            if (ok1) {
                float2 t = *(const float2*)(Tm + (size_t)r1 * 128 + col);
                pp1 += c2 * c2 + c3 * c3;
                tt1 += t.x * t.x + t.y * t.y;
                pt1 += c2 * t.x + c3 * t.y;
            }
        }
#pragma unroll
        for (int msk = 1; msk <= 2; msk <<= 1) {
            pp0 += __shfl_xor_sync(0xffffffffu, pp0, msk);
            tt0 += __shfl_xor_sync(0xffffffffu, tt0, msk);
            pt0 += __shfl_xor_sync(0xffffffffu, pt0, msk);
            pp1 += __shfl_xor_sync(0xffffffffu, pp1, msk);
            tt1 += __shfl_xor_sync(0xffffffffu, tt1, msk);
            pt1 += __shfl_xor_sync(0xffffffffu, pt1, msk);
        }
        if (tig == 0) {
            int lr0 = wm * 16 + grp, lr1 = lr0 + 8;
            atomicAdd(&redf[lr0], pp0);
            atomicAdd(&redf[128 + lr0], tt0);
            atomicAdd(&redf[256 + lr0], pt0);
            atomicAdd(&redf[lr1], pp1);
            atomicAdd(&redf[128 + lr1], tt1);
            atomicAdd(&redf[256 + lr1], pt1);
        }
        __syncthreads();
        if (tid < 128) {
            float l = 0.f;
            if (m0 + tid < n)
                l = 2.f - 2.f * redf[256 + tid] * rsqrtf(redf[tid]) * rsqrtf(redf[128 + tid]);
#pragma unroll
            for (int o = 16; o; o >>= 1) l += __shfl_xor_sync(0xffffffffu, l, o);
            if (lane == 0) redf[320 + wid] = l;
        }
        __syncthreads();
        if (tid == 0)
            atomicAdd(&g_loss, redf[320] + redf[321] + redf[322] + redf[323]);
        return;
    }

#pragma unroll
    for (int ni = 0; ni < 8; ni++) {
        int col = wn * 64 + ni * 8 + tig * 2;
        float2 bv = *(const float2*)(bias + col);
        float c0 = acc[ni][0] + bv.x, c1 = acc[ni][1] + bv.y;
        float c2 = acc[ni][2] + bv.x, c3 = acc[ni][3] + bv.y;
        if (ok0) {
            size_t o0 = (size_t)r0 * 128 + col;
            *(float2*)(outp + o0) = make_float2(c0, c1);
            if (PHASE == 0 && do_emb) {
                float2 xv = *(const float2*)(xsrc + o0);
                float2 pv = *(const float2*)(psrc + o0);
                *(float2*)(emb + o0) = make_float2(c0 + xv.x + pv.x, c1 + xv.y + pv.y);
            }
        }
        if (ok1) {
            size_t o1 = (size_t)r1 * 128 + col;
            *(float2*)(outp + o1) = make_float2(c2, c3);
            if (PHASE == 0 && do_emb) {
                float2 xv = *(const float2*)(xsrc + o1);
                float2 pv = *(const float2*)(psrc + o1);
                *(float2*)(emb + o1) = make_float2(c2 + xv.x + pv.x, c3 + xv.y + pv.y);
            }
        }
        if (PHASE == 1) {
            float s0 = (ok0 ? c0 : 0.f) + (ok1 ? c2 : 0.f);
            float s1 = (ok0 ? c1 : 0.f) + (ok1 ? c3 : 0.f);
            float q0 = (ok0 ? c0 * c0 : 0.f) + (ok1 ? c2 * c2 : 0.f);
            float q1 = (ok0 ? c1 * c1 : 0.f) + (ok1 ? c3 * c3 : 0.f);
#pragma unroll
            for (int msk = 4; msk <= 16; msk <<= 1) {
                s0 += __shfl_xor_sync(0xffffffffu, s0, msk);
                s1 += __shfl_xor_sync(0xffffffffu, s1, msk);
                q0 += __shfl_xor_sync(0xffffffffu, q0, msk);
                q1 += __shfl_xor_sync(0xffffffffu, q1, msk);
            }
            if (grp == 0) {
                atomicAdd(&redf[col], s0);
                atomicAdd(&redf[col + 1], s1);
                atomicAdd(&redf[128 + col], q0);
                atomicAdd(&redf[128 + col + 1], q1);
            }
        }
    }

    if (PHASE == 1) {
        __syncthreads();
        if (tid < 256)
            atomicAdd(&g_stats[set * 256 + tid], redf[tid]);
    }
}

// ---------------------------------------------------------------------------
__global__ void bn_finalize(const float* __restrict__ gamma, int n) {
    int t = threadIdx.x;
    int set = t >> 7, c = t & 127;
    float s = g_stats[set * 256 + c];
    float q = g_stats[set * 256 + 128 + c];
    float mu = s / (float)n;
    float var = q / (float)n - mu * mu;
    float g = gamma[c] * rsqrtf(var + 1e-5f);
    g_bnp[set * 256 + c] = mu;
    g_bnp[set * 256 + 128 + c] = g;
}

__global__ void finish_kernel(float* __restrict__ out, int n, size_t idx) {
    out[idx] = g_loss / (float)n;
}

// ---------------------------------------------------------------------------
extern "C" void kernel_launch(void* const* d_in, const int* in_sizes, int n_in,
                              void* d_out, int out_size) {
    const float* x     = (const float*)d_in[0];
    const float* perb  = (const float*)d_in[1];
    const int*   erow  = (const int*)d_in[2];
    const int*   ecol  = (const int*)d_in[3];
    const float* eval  = (const float*)d_in[4];
    const float* W     = (const float*)d_in[5];
    const float* b     = (const float*)d_in[6];
    const float* Wt    = (const float*)d_in[7];
    const float* bt    = (const float*)d_in[8];
    const float* W1    = (const float*)d_in[9];
    const float* b1    = (const float*)d_in[10];
    const float* gamma = (const float*)d_in[11];
    const float* beta  = (const float*)d_in[12];
    const float* alpha = (const float*)d_in[13];
    const float* W2    = (const float*)d_in[14];
    const float* b2    = (const float*)d_in[15];

    const int n = in_sizes[0] / DD;
    const int E = in_sizes[2];
    float* out = (float*)d_out;

    float* buf = nullptr;
    cudaGetSymbolAddress((void**)&buf, g_buf);

    float* AX  = buf + 0 * NB;   // adj@x
    float* AS  = buf + 1 * NB;   // adj@(x+perb)
    float* OX  = buf + 2 * NB;   // online_x
    float* TY  = buf + 3 * NB;   // target_y
    float* EX  = buf + 4 * NB;   // enc_x2 = online_y
    float* TX  = buf + 5 * NB;   // target_x
    float* U1  = buf + 6 * NB;
    float* U2  = buf + 7 * NB;

    cudaFuncSetAttribute(fgemm<0>, cudaFuncAttributeMaxDynamicSharedMemorySize, SMEM_BYTES);
    cudaFuncSetAttribute(fgemm<1>, cudaFuncAttributeMaxDynamicSharedMemorySize, SMEM_BYTES);
    cudaFuncSetAttribute(fgemm<2>, cudaFuncAttributeMaxDynamicSharedMemorySize, SMEM_BYTES);

    // init + CSR build
    init_kernel<<<(n + 1 + 255) / 256, 256>>>(W, Wt, W1, W2, n);
    hist_kernel<<<(E + 255) / 256, 256>>>(erow, E);
    scan_kernel<<<1, 1024>>>(n);
    scatter_kernel<<<(E + 255) / 256, 256>>>(erow, ecol, eval, E);

    // gather-only SpMM (no atomics)
    spmm_csr<<<(int)(((long long)n * 32 + 255) / 256), 256>>>(x, perb, AX, AS, n);

    const int gbx = (n + 127) / 128;
    dim3 g4(4, gbx, 1), g2(2, gbx, 1);

    // encoder: OX, TY, EX(+emb), TX
    fgemm<0><<<g4, 512, SMEM_BYTES>>>(AX, AS, OX, TY, EX, TX, U1, U2,
                                      b, bt, b1, b2, beta, alpha, x, perb, out, n);
    // predictor L1 + BN stats
    fgemm<1><<<g2, 512, SMEM_BYTES>>>(AX, AS, OX, TY, EX, TX, U1, U2,
                                      b, bt, b1, b2, beta, alpha, x, perb, out, n);
    bn_finalize<<<1, 256>>>(gamma, n);
    // predictor L2 (fused BN+PReLU) + fused BYOL loss
    fgemm<2><<<g2, 512, SMEM_BYTES>>>(AX, AS, OX, TY, EX, TX, U1, U2,
                                      b, bt, b1, b2, beta, alpha, x, perb, out, n);

    finish_kernel<<<1, 1>>>(out, n, (size_t)n * DD);
}

// round 9
// speedup vs baseline: 3.2939x; 1.0677x over previous
#include <cuda_runtime.h>
#include <stdint.h>

#define DD 128
#define NMAX 50000
#define EMAX 800000
#define NB ((size_t)NMAX * DD)

// scratch (static device memory — no allocs)
__device__ __align__(16) float g_buf[6 * NB];
__device__ __align__(16) float g_w[4 * DD * DD];   // tf32-rounded W, Wt, W1, W2
__device__ __align__(16) float g_ww1[DD * DD];     // rnd(W_r @ W1_r)
__device__ float g_bb1[DD];                        // b @ W1_r + b1
__device__ float g_stats[512];   // [set][{sum,sumsq}][128]
__device__ float g_bnp[512];     // [set][{mu, gamma*rstd}][128]
__device__ float g_loss;
// CSR build
__device__ int   g_cnt[NMAX + 1];
__device__ int   g_cursor[NMAX];
__device__ __align__(8) int2 g_epk[EMAX];          // packed {col, val-bits}

__device__ __forceinline__ float rnd_tf32(float f) {
    uint32_t u;
    asm("cvt.rna.tf32.f32 %0, %1;" : "=r"(u) : "f"(f));
    return __uint_as_float(u);
}

__device__ __forceinline__ uint32_t rndu(uint32_t u) {
    uint32_t o;
    asm("cvt.rna.tf32.f32 %0, %1;" : "=r"(o) : "f"(__uint_as_float(u)));
    return o;
}

__device__ __forceinline__ uint32_t bnfrag(uint32_t u, float g, float bp, float alpha) {
    float v = __uint_as_float(u);
    v = fmaf(v, g, bp);
    v = fmaxf(v, 0.f) + alpha * fminf(v, 0.f);
    uint32_t o;
    asm("cvt.rna.tf32.f32 %0, %1;" : "=r"(o) : "f"(v));
    return o;
}

__device__ __forceinline__ void mma_tf32(float& d0, float& d1, float& d2, float& d3,
                                         uint32_t a0, uint32_t a1, uint32_t a2, uint32_t a3,
                                         uint32_t b0, uint32_t b1) {
    asm volatile(
        "mma.sync.aligned.m16n8k8.row.col.f32.tf32.tf32.f32 "
        "{%0,%1,%2,%3}, {%4,%5,%6,%7}, {%8,%9}, {%0,%1,%2,%3};"
        : "+f"(d0), "+f"(d1), "+f"(d2), "+f"(d3)
        : "r"(a0), "r"(a1), "r"(a2), "r"(a3), "r"(b0), "r"(b1));
}

__device__ __forceinline__ uint32_t smem_u32(const void* p) {
    uint32_t a;
    asm("{ .reg .u64 t; cvta.to.shared.u64 t, %1; cvt.u32.u64 %0, t; }" : "=r"(a) : "l"(p));
    return a;
}

__device__ __forceinline__ void cp16(uint32_t dst, const void* src, bool pred) {
    int sz = pred ? 16 : 0;
    asm volatile("cp.async.cg.shared.global [%0], [%1], 16, %2;"
                 :: "r"(dst), "l"(src), "r"(sz) : "memory");
}
#define CP_COMMIT() asm volatile("cp.async.commit_group;" ::: "memory")

// ---------------------------------------------------------------------------
// init: zero hist/stats/loss; round weight matrices into g_w
// ---------------------------------------------------------------------------
__global__ void init_kernel(const float* __restrict__ W, const float* __restrict__ Wt,
                            const float* __restrict__ W1, const float* __restrict__ W2,
                            int n) {
    int i = blockIdx.x * blockDim.x + threadIdx.x;
    if (i < 512) g_stats[i] = 0.f;
    if (i == 0) g_loss = 0.f;
    if (i <= n) g_cnt[i] = 0;
    if (i < DD * DD) {
        g_w[i]               = rnd_tf32(W[i]);
        g_w[DD * DD + i]     = rnd_tf32(Wt[i]);
        g_w[2 * DD * DD + i] = rnd_tf32(W1[i]);
        g_w[3 * DD * DD + i] = rnd_tf32(W2[i]);
    }
}

// ---------------------------------------------------------------------------
// wprod: WW1 = rnd(W_r @ W1_r); bb1 = b @ W1_r + b1
// ---------------------------------------------------------------------------
__global__ void wprod_kernel(const float* __restrict__ b, const float* __restrict__ b1) {
    int idx = blockIdx.x * 256 + threadIdx.x;     // 0..16383
    int i = idx >> 7, j = idx & 127;
    const float* W1r = g_w + 2 * DD * DD;
    float s = 0.f;
#pragma unroll 8
    for (int k = 0; k < 128; k++)
        s = fmaf(g_w[i * 128 + k], W1r[k * 128 + j], s);
    g_ww1[idx] = rnd_tf32(s);
    if (idx < 128) {
        float t = 0.f;
        for (int k = 0; k < 128; k++)
            t = fmaf(b[k], W1r[k * 128 + idx], t);
        g_bb1[idx] = t + b1[idx];
    }
}

// ---------------------------------------------------------------------------
// CSR build: histogram -> scan -> scatter (packed payload)
// ---------------------------------------------------------------------------
__global__ void hist_kernel(const int* __restrict__ erow, int E) {
    int i = blockIdx.x * blockDim.x + threadIdx.x;
    if (i < E) atomicAdd(&g_cnt[erow[i] + 1], 1);
}

__global__ __launch_bounds__(1024)
void scan_kernel(int n) {
    const int n1 = n + 1;
    const int t = threadIdx.x;
    const int chunk = (n1 + 1023) / 1024;
    const int lo = t * chunk;
    const int hi = min(lo + chunk, n1);
    int s = 0;
    for (int i = lo; i < hi; i++) s += g_cnt[i];
    __shared__ int sm[1024];
    sm[t] = s;
    __syncthreads();
    for (int off = 1; off < 1024; off <<= 1) {
        int v = (t >= off) ? sm[t - off] : 0;
        __syncthreads();
        sm[t] += v;
        __syncthreads();
    }
    int run = sm[t] - s;
    for (int i = lo; i < hi; i++) {
        run += g_cnt[i];
        g_cnt[i] = run;              // inclusive scan: start offset of row i
        if (i < n) g_cursor[i] = run;
    }
}

__global__ void scatter_kernel(const int* __restrict__ erow, const int* __restrict__ ecol,
                               const float* __restrict__ eval, int E) {
    int i = blockIdx.x * blockDim.x + threadIdx.x;
    if (i >= E) return;
    int r = erow[i];
    int pos = atomicAdd(&g_cursor[r], 1);
    g_epk[pos] = make_int2(ecol[i], __float_as_int(eval[i]));
}

// ---------------------------------------------------------------------------
// CSR SpMM: one warp per row, uniform edge reads (no shfl), 2-edge unroll.
// AX[r] = sum v*x[c];  AS[r] = sum v*(x[c]+perb[c])
// ---------------------------------------------------------------------------
__global__ __launch_bounds__(256)
void spmm_csr(const float* __restrict__ x, const float* __restrict__ perb,
              float* __restrict__ ax, float* __restrict__ as, int n) {
    int r = (int)((blockIdx.x * (size_t)blockDim.x + threadIdx.x) >> 5);
    if (r >= n) return;
    int lane = threadIdx.x & 31;
    int e = g_cnt[r], end = g_cnt[r + 1];
    const int off = lane * 4;
    float4 a0 = make_float4(0.f, 0.f, 0.f, 0.f);
    float4 s0 = make_float4(0.f, 0.f, 0.f, 0.f);
    float4 a1 = make_float4(0.f, 0.f, 0.f, 0.f);
    float4 s1 = make_float4(0.f, 0.f, 0.f, 0.f);
    for (; e + 2 <= end; e += 2) {
        int2 p0 = g_epk[e];
        int2 p1 = g_epk[e + 1];
        float v0 = __int_as_float(p0.y);
        float v1 = __int_as_float(p1.y);
        size_t c0 = (size_t)p0.x * 128 + off;
        size_t c1 = (size_t)p1.x * 128 + off;
        float4 xv0 = *(const float4*)(x + c0);
        float4 pv0 = *(const float4*)(perb + c0);
        float4 xv1 = *(const float4*)(x + c1);
        float4 pv1 = *(const float4*)(perb + c1);
        a0.x = fmaf(v0, xv0.x, a0.x); a0.y = fmaf(v0, xv0.y, a0.y);
        a0.z = fmaf(v0, xv0.z, a0.z); a0.w = fmaf(v0, xv0.w, a0.w);
        s0.x = fmaf(v0, xv0.x + pv0.x, s0.x); s0.y = fmaf(v0, xv0.y + pv0.y, s0.y);
        s0.z = fmaf(v0, xv0.z + pv0.z, s0.z); s0.w = fmaf(v0, xv0.w + pv0.w, s0.w);
        a1.x = fmaf(v1, xv1.x, a1.x); a1.y = fmaf(v1, xv1.y, a1.y);
        a1.z = fmaf(v1, xv1.z, a1.z); a1.w = fmaf(v1, xv1.w, a1.w);
        s1.x = fmaf(v1, xv1.x + pv1.x, s1.x); s1.y = fmaf(v1, xv1.y + pv1.y, s1.y);
        s1.z = fmaf(v1, xv1.z + pv1.z, s1.z); s1.w = fmaf(v1, xv1.w + pv1.w, s1.w);
    }
    if (e < end) {
        int2 p0 = g_epk[e];
        float v0 = __int_as_float(p0.y);
        size_t c0 = (size_t)p0.x * 128 + off;
        float4 xv0 = *(const float4*)(x + c0);
        float4 pv0 = *(const float4*)(perb + c0);
        a0.x = fmaf(v0, xv0.x, a0.x); a0.y = fmaf(v0, xv0.y, a0.y);
        a0.z = fmaf(v0, xv0.z, a0.z); a0.w = fmaf(v0, xv0.w, a0.w);
        s0.x = fmaf(v0, xv0.x + pv0.x, s0.x); s0.y = fmaf(v0, xv0.y + pv0.y, s0.y);
        s0.z = fmaf(v0, xv0.z + pv0.z, s0.z); s0.w = fmaf(v0, xv0.w + pv0.w, s0.w);
    }
    a0.x += a1.x; a0.y += a1.y; a0.z += a1.z; a0.w += a1.w;
    s0.x += s1.x; s0.y += s1.y; s0.z += s1.z; s0.w += s1.w;
    size_t ro = (size_t)r * 128 + off;
    *(float4*)(ax + ro) = a0;
    *(float4*)(as + ro) = s0;
}

// ---------------------------------------------------------------------------
// Pipelined tf32 GEMM, cp.async ping-pong, BK=32 x 4 chunks, 512 thr / 16 warps.
// PHASE 0 (5 sets): 0: TY=AX@Wt+bt       1: U1=AX@WW1+bb1 (stats0)
//                   2: TX=AS@Wt+bt       3: emb=AS@W+b+x+perb (no EX store)
//                   4: U2=AS@WW1+bb1 (stats1)
// PHASE 2 (2 sets): p=PReLU(BN(U))@W2+b2 (no store), fused BYOL loss vs T
// ---------------------------------------------------------------------------
#define AP_ 36
#define BP_ 136
#define ACH (128 * AP_)
#define BCH (32 * BP_)
#define RED_OFF (2 * ACH + 2 * BCH)
#define SMEM_BYTES ((RED_OFF + 384 + 256) * 4)

template <int PHASE>
__global__ __launch_bounds__(512, 2)
void fgemm(const float* __restrict__ AX, const float* __restrict__ AS,
           float* __restrict__ TY, float* __restrict__ TX,
           float* __restrict__ U1, float* __restrict__ U2,
           const float* __restrict__ b, const float* __restrict__ bt,
           const float* __restrict__ b2,
           const float* __restrict__ beta, const float* __restrict__ alphap,
           const float* __restrict__ xsrc, const float* __restrict__ psrc,
           float* __restrict__ emb, int n) {
    extern __shared__ float smf[];
    uint32_t sb = smem_u32(smf);
    float* redf = smf + RED_OFF;
    float* sG   = smf + RED_OFF + 384;
    float* sBp  = sG + 128;

    const int tid = threadIdx.x;
    const int wid = tid >> 5;
    const int lane = tid & 31;
    const int grp = lane >> 2;
    const int tig = lane & 3;
    const int wm = wid >> 1;
    const int wn = wid & 1;
    const int set = blockIdx.x;
    const int m0 = blockIdx.y * 128;

    const float* A;
    const float* Bm;
    const float* bias;
    float* outp = nullptr;
    const float* Tm = nullptr;
    bool do_emb = false, do_stats = false;
    int statset = 0;
    if (PHASE == 0) {
        A = (set >= 2) ? AS : AX;
        if (set == 0)      { Bm = g_w + DD * DD; bias = bt;    outp = TY; }
        else if (set == 1) { Bm = g_ww1;         bias = g_bb1; outp = U1; do_stats = true; statset = 0; }
        else if (set == 2) { Bm = g_w + DD * DD; bias = bt;    outp = TX; }
        else if (set == 3) { Bm = g_w;           bias = b;     outp = emb; do_emb = true; }
        else               { Bm = g_ww1;         bias = g_bb1; outp = U2; do_stats = true; statset = 1; }
    } else {
        A = set ? U2 : U1;
        Bm = g_w + 3 * DD * DD;
        bias = b2;
        Tm = set ? TY : TX;
    }

    if (tid < 384) redf[tid] = 0.f;
    float alpha = 0.f;
    if (PHASE == 2) {
        alpha = __ldg(alphap);
        if (tid < 128) {
            float mu = g_bnp[set * 256 + tid];
            float g  = g_bnp[set * 256 + 128 + tid];
            sG[tid] = g;
            sBp[tid] = beta[tid] - mu * g;
        }
    }

    float acc[8][4];
#pragma unroll
    for (int j = 0; j < 8; j++)
#pragma unroll
        for (int q = 0; q < 4; q++) acc[j][q] = 0.f;

    auto issue = [&](int c, int s) {
        const int kb = c * 32;
#pragma unroll
        for (int j = 0; j < 2; j++) {
            int f = tid + j * 512;
            int row = f >> 3, c4 = f & 7;
            uint32_t dst = sb + (uint32_t)((s * ACH + row * AP_ + c4 * 4) * 4);
            cp16(dst, A + (size_t)(m0 + row) * 128 + kb + c4 * 4, (m0 + row) < n);
        }
#pragma unroll
        for (int j = 0; j < 2; j++) {
            int f = tid + j * 512;
            int kr = f >> 5, c4 = f & 31;
            uint32_t dst = sb + (uint32_t)((2 * ACH + s * BCH + kr * BP_ + c4 * 4) * 4);
            cp16(dst, Bm + (size_t)(kb + kr) * 128 + c4 * 4, true);
        }
        CP_COMMIT();
    };

    issue(0, 0);
    for (int c = 0; c < 4; c++) {
        if (c < 3) {
            issue(c + 1, (c + 1) & 1);
            asm volatile("cp.async.wait_group 1;" ::: "memory");
        } else {
            asm volatile("cp.async.wait_group 0;" ::: "memory");
        }
        __syncthreads();
        const uint32_t* Ab = (const uint32_t*)(smf + (c & 1) * ACH);
        const uint32_t* Bb = (const uint32_t*)(smf + 2 * ACH + (c & 1) * BCH);
#pragma unroll
        for (int ks = 0; ks < 4; ks++) {
            const int k0 = ks * 8;
            const uint32_t* a0p = Ab + (wm * 16 + grp) * AP_ + k0 + tig;
            const uint32_t* a1p = a0p + 8 * AP_;
            uint32_t af0 = a0p[0], af1 = a1p[0], af2 = a0p[4], af3 = a1p[4];
            if (PHASE == 2) {
                int kA = c * 32 + k0 + tig;
                float gA = sG[kA], bA = sBp[kA];
                float gB = sG[kA + 4], bB = sBp[kA + 4];
                af0 = bnfrag(af0, gA, bA, alpha);
                af1 = bnfrag(af1, gA, bA, alpha);
                af2 = bnfrag(af2, gB, bB, alpha);
                af3 = bnfrag(af3, gB, bB, alpha);
            } else {
                af0 = rndu(af0); af1 = rndu(af1);
                af2 = rndu(af2); af3 = rndu(af3);
            }
#pragma unroll
            for (int ni = 0; ni < 8; ni++) {
                const uint32_t* bp = Bb + (k0 + tig) * BP_ + wn * 64 + ni * 8 + grp;
                uint32_t b0 = bp[0], b1v = bp[4 * BP_];
                mma_tf32(acc[ni][0], acc[ni][1], acc[ni][2], acc[ni][3],
                         af0, af1, af2, af3, b0, b1v);
            }
        }
        __syncthreads();
    }

    const int r0 = m0 + wm * 16 + grp;
    const int r1 = r0 + 8;
    const bool ok0 = r0 < n, ok1 = r1 < n;

    if (PHASE == 2) {
        float pp0 = 0.f, tt0 = 0.f, pt0 = 0.f;
        float pp1 = 0.f, tt1 = 0.f, pt1 = 0.f;
#pragma unroll
        for (int ni = 0; ni < 8; ni++) {
            int col = wn * 64 + ni * 8 + tig * 2;
            float2 bv = *(const float2*)(bias + col);
            float c0 = acc[ni][0] + bv.x, c1 = acc[ni][1] + bv.y;
            float c2 = acc[ni][2] + bv.x, c3 = acc[ni][3] + bv.y;
            if (ok0) {
                float2 t = *(const float2*)(Tm + (size_t)r0 * 128 + col);
                pp0 += c0 * c0 + c1 * c1;
                tt0 += t.x * t.x + t.y * t.y;
                pt0 += c0 * t.x + c1 * t.y;
            }
            if (ok1) {
                float2 t = *(const float2*)(Tm + (size_t)r1 * 128 + col);
                pp1 += c2 * c2 + c3 * c3;
                tt1 += t.x * t.x + t.y * t.y;
                pt1 += c2 * t.x + c3 * t.y;
            }
        }
#pragma unroll
        for (int msk = 1; msk <= 2; msk <<= 1) {
            pp0 += __shfl_xor_sync(0xffffffffu, pp0, msk);
            tt0 += __shfl_xor_sync(0xffffffffu, tt0, msk);
            pt0 += __shfl_xor_sync(0xffffffffu, pt0, msk);
            pp1 += __shfl_xor_sync(0xffffffffu, pp1, msk);
            tt1 += __shfl_xor_sync(0xffffffffu, tt1, msk);
            pt1 += __shfl_xor_sync(0xffffffffu, pt1, msk);
        }
        if (tig == 0) {
            int lr0 = wm * 16 + grp, lr1 = lr0 + 8;
            atomicAdd(&redf[lr0], pp0);
            atomicAdd(&redf[128 + lr0], tt0);
            atomicAdd(&redf[256 + lr0], pt0);
            atomicAdd(&redf[lr1], pp1);
            atomicAdd(&redf[128 + lr1], tt1);
            atomicAdd(&redf[256 + lr1], pt1);
        }
        __syncthreads();
        if (tid < 128) {
            float l = 0.f;
            if (m0 + tid < n)
                l = 2.f - 2.f * redf[256 + tid] * rsqrtf(redf[tid]) * rsqrtf(redf[128 + tid]);
#pragma unroll
            for (int o = 16; o; o >>= 1) l += __shfl_xor_sync(0xffffffffu, l, o);
            if (lane == 0) redf[320 + wid] = l;
        }
        __syncthreads();
        if (tid == 0)
            atomicAdd(&g_loss, redf[320] + redf[321] + redf[322] + redf[323]);
        return;
    }

    // PHASE 0 store epilogue
#pragma unroll
    for (int ni = 0; ni < 8; ni++) {
        int col = wn * 64 + ni * 8 + tig * 2;
        float2 bv = *(const float2*)(bias + col);
        float c0 = acc[ni][0] + bv.x, c1 = acc[ni][1] + bv.y;
        float c2 = acc[ni][2] + bv.x, c3 = acc[ni][3] + bv.y;
        if (ok0) {
            size_t o0 = (size_t)r0 * 128 + col;
            if (do_emb) {
                float2 xv = *(const float2*)(xsrc + o0);
                float2 pv = *(const float2*)(psrc + o0);
                *(float2*)(outp + o0) = make_float2(c0 + xv.x + pv.x, c1 + xv.y + pv.y);
            } else {
                *(float2*)(outp + o0) = make_float2(c0, c1);
            }
        }
        if (ok1) {
            size_t o1 = (size_t)r1 * 128 + col;
            if (do_emb) {
                float2 xv = *(const float2*)(xsrc + o1);
                float2 pv = *(const float2*)(psrc + o1);
                *(float2*)(outp + o1) = make_float2(c2 + xv.x + pv.x, c3 + xv.y + pv.y);
            } else {
                *(float2*)(outp + o1) = make_float2(c2, c3);
            }
        }
        if (do_stats) {
            float s0 = (ok0 ? c0 : 0.f) + (ok1 ? c2 : 0.f);
            float s1 = (ok0 ? c1 : 0.f) + (ok1 ? c3 : 0.f);
            float q0 = (ok0 ? c0 * c0 : 0.f) + (ok1 ? c2 * c2 : 0.f);
            float q1 = (ok0 ? c1 * c1 : 0.f) + (ok1 ? c3 * c3 : 0.f);
#pragma unroll
            for (int msk = 4; msk <= 16; msk <<= 1) {
                s0 += __shfl_xor_sync(0xffffffffu, s0, msk);
                s1 += __shfl_xor_sync(0xffffffffu, s1, msk);
                q0 += __shfl_xor_sync(0xffffffffu, q0, msk);
                q1 += __shfl_xor_sync(0xffffffffu, q1, msk);
            }
            if (grp == 0) {
                atomicAdd(&redf[col], s0);
                atomicAdd(&redf[col + 1], s1);
                atomicAdd(&redf[128 + col], q0);
                atomicAdd(&redf[128 + col + 1], q1);
            }
        }
    }

    if (do_stats) {
        __syncthreads();
        if (tid < 256)
            atomicAdd(&g_stats[statset * 256 + tid], redf[tid]);
    }
}

// ---------------------------------------------------------------------------
__global__ void bn_finalize(const float* __restrict__ gamma, int n) {
    int t = threadIdx.x;
    int set = t >> 7, c = t & 127;
    float s = g_stats[set * 256 + c];
    float q = g_stats[set * 256 + 128 + c];
    float mu = s / (float)n;
    float var = q / (float)n - mu * mu;
    float g = gamma[c] * rsqrtf(var + 1e-5f);
    g_bnp[set * 256 + c] = mu;
    g_bnp[set * 256 + 128 + c] = g;
}

__global__ void finish_kernel(float* __restrict__ out, int n, size_t idx) {
    out[idx] = g_loss / (float)n;
}

// ---------------------------------------------------------------------------
extern "C" void kernel_launch(void* const* d_in, const int* in_sizes, int n_in,
                              void* d_out, int out_size) {
    const float* x     = (const float*)d_in[0];
    const float* perb  = (const float*)d_in[1];
    const int*   erow  = (const int*)d_in[2];
    const int*   ecol  = (const int*)d_in[3];
    const float* eval  = (const float*)d_in[4];
    const float* W     = (const float*)d_in[5];
    const float* b     = (const float*)d_in[6];
    const float* Wt    = (const float*)d_in[7];
    const float* bt    = (const float*)d_in[8];
    const float* W1    = (const float*)d_in[9];
    const float* b1    = (const float*)d_in[10];
    const float* gamma = (const float*)d_in[11];
    const float* beta  = (const float*)d_in[12];
    const float* alpha = (const float*)d_in[13];
    const float* W2    = (const float*)d_in[14];
    const float* b2    = (const float*)d_in[15];

    const int n = in_sizes[0] / DD;
    const int E = in_sizes[2];
    float* out = (float*)d_out;

    float* buf = nullptr;
    cudaGetSymbolAddress((void**)&buf, g_buf);

    float* AX  = buf + 0 * NB;   // adj@x
    float* AS  = buf + 1 * NB;   // adj@(x+perb)
    float* TY  = buf + 2 * NB;   // target_y
    float* TX  = buf + 3 * NB;   // target_x
    float* U1  = buf + 4 * NB;
    float* U2  = buf + 5 * NB;

    cudaFuncSetAttribute(fgemm<0>, cudaFuncAttributeMaxDynamicSharedMemorySize, SMEM_BYTES);
    cudaFuncSetAttribute(fgemm<2>, cudaFuncAttributeMaxDynamicSharedMemorySize, SMEM_BYTES);

    // init + composed weights + CSR build
    init_kernel<<<(n + 1 + 255) / 256, 256>>>(W, Wt, W1, W2, n);
    wprod_kernel<<<64, 256>>>(b, b1);
    hist_kernel<<<(E + 255) / 256, 256>>>(erow, E);
    scan_kernel<<<1, 1024>>>(n);
    scatter_kernel<<<(E + 255) / 256, 256>>>(erow, ecol, eval, E);

    // gather-only SpMM (no atomics)
    spmm_csr<<<(int)(((long long)n * 32 + 255) / 256), 256>>>(x, perb, AX, AS, n);

    const int gbx = (n + 127) / 128;
    dim3 g5(5, gbx, 1), g2(2, gbx, 1);

    // merged encoder + predictor L1: TY, U1(stats), TX, emb, U2(stats)
    fgemm<0><<<g5, 512, SMEM_BYTES>>>(AX, AS, TY, TX, U1, U2,
                                      b, bt, b2, beta, alpha, x, perb, out, n);
    bn_finalize<<<1, 256>>>(gamma, n);
    // predictor L2 (fused BN+PReLU) + fused BYOL loss
    fgemm<2><<<g2, 512, SMEM_BYTES>>>(AX, AS, TY, TX, U1, U2,
                                      b, bt, b2, beta, alpha, x, perb, out, n);

    finish_kernel<<<1, 1>>>(out, n, (size_t)n * DD);
}

// round 10
// speedup vs baseline: 4.1133x; 1.2488x over previous
#include <cuda_runtime.h>
#include <stdint.h>

#define DD 128
#define NMAX 50000
#define EMAX 800000
#define NB ((size_t)NMAX * DD)

// scratch (static device memory — no allocs)
__device__ __align__(16) float g_buf[6 * NB];
__device__ __align__(16) float g_w[4 * DD * DD];   // tf32-rounded W, Wt, W1, W2
__device__ __align__(16) float g_ww1[DD * DD];     // rnd(W_r @ W1_r)
__device__ float g_bb1[DD];                        // b @ W1_r + b1
__device__ float g_stats[512];   // [set][{sum,sumsq}][128]
__device__ float g_bnp[512];     // [set][{mu, gamma*rstd}][128]
__device__ float g_loss;
// CSR build
__device__ int   g_cnt[NMAX + 1];
__device__ int   g_cursor[NMAX];
__device__ int   g_blksum[64];
__device__ int   g_blkoff[64];
__device__ __align__(8) int2 g_epk[EMAX];          // packed {col, val-bits}

__device__ __forceinline__ float rnd_tf32(float f) {
    uint32_t u;
    asm("cvt.rna.tf32.f32 %0, %1;" : "=r"(u) : "f"(f));
    return __uint_as_float(u);
}

__device__ __forceinline__ uint32_t rndu(uint32_t u) {
    uint32_t o;
    asm("cvt.rna.tf32.f32 %0, %1;" : "=r"(o) : "f"(__uint_as_float(u)));
    return o;
}

__device__ __forceinline__ uint32_t bnfrag(uint32_t u, float g, float bp, float alpha) {
    float v = __uint_as_float(u);
    v = fmaf(v, g, bp);
    v = fmaxf(v, 0.f) + alpha * fminf(v, 0.f);
    uint32_t o;
    asm("cvt.rna.tf32.f32 %0, %1;" : "=r"(o) : "f"(v));
    return o;
}

__device__ __forceinline__ void mma_tf32(float& d0, float& d1, float& d2, float& d3,
                                         uint32_t a0, uint32_t a1, uint32_t a2, uint32_t a3,
                                         uint32_t b0, uint32_t b1) {
    asm volatile(
        "mma.sync.aligned.m16n8k8.row.col.f32.tf32.tf32.f32 "
        "{%0,%1,%2,%3}, {%4,%5,%6,%7}, {%8,%9}, {%0,%1,%2,%3};"
        : "+f"(d0), "+f"(d1), "+f"(d2), "+f"(d3)
        : "r"(a0), "r"(a1), "r"(a2), "r"(a3), "r"(b0), "r"(b1));
}

__device__ __forceinline__ uint32_t smem_u32(const void* p) {
    uint32_t a;
    asm("{ .reg .u64 t; cvta.to.shared.u64 t, %1; cvt.u32.u64 %0, t; }" : "=r"(a) : "l"(p));
    return a;
}

__device__ __forceinline__ void cp16(uint32_t dst, const void* src, bool pred) {
    int sz = pred ? 16 : 0;
    asm volatile("cp.async.cg.shared.global [%0], [%1], 16, %2;"
                 :: "r"(dst), "l"(src), "r"(sz) : "memory");
}
#define CP_COMMIT() asm volatile("cp.async.commit_group;" ::: "memory")

// ---------------------------------------------------------------------------
// init: zero hist/stats/loss; round weight matrices into g_w
// ---------------------------------------------------------------------------
__global__ void init_kernel(const float* __restrict__ W, const float* __restrict__ Wt,
                            const float* __restrict__ W1, const float* __restrict__ W2,
                            int n) {
    int i = blockIdx.x * blockDim.x + threadIdx.x;
    if (i < 512) g_stats[i] = 0.f;
    if (i == 0) g_loss = 0.f;
    if (i <= n) g_cnt[i] = 0;
    if (i < DD * DD) {
        g_w[i]               = rnd_tf32(W[i]);
        g_w[DD * DD + i]     = rnd_tf32(Wt[i]);
        g_w[2 * DD * DD + i] = rnd_tf32(W1[i]);
        g_w[3 * DD * DD + i] = rnd_tf32(W2[i]);
    }
}

// ---------------------------------------------------------------------------
// wprod: WW1 = rnd(W_r @ W1_r); bb1 = b @ W1_r + b1
// ---------------------------------------------------------------------------
__global__ void wprod_kernel(const float* __restrict__ b, const float* __restrict__ b1) {
    int idx = blockIdx.x * 256 + threadIdx.x;     // 0..16383
    int i = idx >> 7, j = idx & 127;
    const float* W1r = g_w + 2 * DD * DD;
    float s = 0.f;
#pragma unroll 8
    for (int k = 0; k < 128; k++)
        s = fmaf(g_w[i * 128 + k], W1r[k * 128 + j], s);
    g_ww1[idx] = rnd_tf32(s);
    if (idx < 128) {
        float t = 0.f;
        for (int k = 0; k < 128; k++)
            t = fmaf(b[k], W1r[k * 128 + idx], t);
        g_bb1[idx] = t + b1[idx];
    }
}

// ---------------------------------------------------------------------------
// CSR build: histogram -> two-level scan -> scatter (packed payload)
// ---------------------------------------------------------------------------
__global__ void hist_kernel(const int* __restrict__ erow, int E) {
    int i = blockIdx.x * blockDim.x + threadIdx.x;
    if (i < E) atomicAdd(&g_cnt[erow[i] + 1], 1);
}

// level-1: per-block (1024 elems) inclusive scan, emit block totals
__global__ __launch_bounds__(1024)
void scanA_kernel(int n) {
    __shared__ int sm[1024];
    int t = threadIdx.x;
    int i = blockIdx.x * 1024 + t;
    int v = (i <= n) ? g_cnt[i] : 0;
    sm[t] = v;
    __syncthreads();
#pragma unroll
    for (int off = 1; off < 1024; off <<= 1) {
        int u = (t >= off) ? sm[t - off] : 0;
        __syncthreads();
        sm[t] += u;
        __syncthreads();
    }
    if (i <= n) g_cnt[i] = sm[t];
    if (t == 1023) g_blksum[blockIdx.x] = sm[1023];
}

// level-2: exclusive scan of block totals (<=64 blocks)
__global__ void scanB_kernel(int nb) {
    __shared__ int sm[64];
    int t = threadIdx.x;                 // 64 threads
    int v = (t < nb) ? g_blksum[t] : 0;
    sm[t] = v;
    __syncthreads();
#pragma unroll
    for (int off = 1; off < 64; off <<= 1) {
        int u = (t >= off) ? sm[t - off] : 0;
        __syncthreads();
        sm[t] += u;
        __syncthreads();
    }
    if (t < nb) g_blkoff[t] = sm[t] - v;   // exclusive
}

// level-3: add block offsets, emit cursors
__global__ __launch_bounds__(1024)
void scanC_kernel(int n) {
    int i = blockIdx.x * 1024 + threadIdx.x;
    if (i <= n) {
        int v = g_cnt[i] + g_blkoff[blockIdx.x];
        g_cnt[i] = v;
        if (i < n) g_cursor[i] = v;
    }
}

__global__ void scatter_kernel(const int* __restrict__ erow, const int* __restrict__ ecol,
                               const float* __restrict__ eval, int E) {
    int i = blockIdx.x * blockDim.x + threadIdx.x;
    if (i >= E) return;
    int r = erow[i];
    int pos = atomicAdd(&g_cursor[r], 1);
    g_epk[pos] = make_int2(ecol[i], __float_as_int(eval[i]));
}

// ---------------------------------------------------------------------------
// CSR SpMM: one warp per row, uniform edge reads, 2-edge unroll.
// ---------------------------------------------------------------------------
__global__ __launch_bounds__(256)
void spmm_csr(const float* __restrict__ x, const float* __restrict__ perb,
              float* __restrict__ ax, float* __restrict__ as, int n) {
    int r = (int)((blockIdx.x * (size_t)blockDim.x + threadIdx.x) >> 5);
    if (r >= n) return;
    int lane = threadIdx.x & 31;
    int e = g_cnt[r], end = g_cnt[r + 1];
    const int off = lane * 4;
    float4 a0 = make_float4(0.f, 0.f, 0.f, 0.f);
    float4 s0 = make_float4(0.f, 0.f, 0.f, 0.f);
    float4 a1 = make_float4(0.f, 0.f, 0.f, 0.f);
    float4 s1 = make_float4(0.f, 0.f, 0.f, 0.f);
    for (; e + 2 <= end; e += 2) {
        int2 p0 = g_epk[e];
        int2 p1 = g_epk[e + 1];
        float v0 = __int_as_float(p0.y);
        float v1 = __int_as_float(p1.y);
        size_t c0 = (size_t)p0.x * 128 + off;
        size_t c1 = (size_t)p1.x * 128 + off;
        float4 xv0 = *(const float4*)(x + c0);
        float4 pv0 = *(const float4*)(perb + c0);
        float4 xv1 = *(const float4*)(x + c1);
        float4 pv1 = *(const float4*)(perb + c1);
        a0.x = fmaf(v0, xv0.x, a0.x); a0.y = fmaf(v0, xv0.y, a0.y);
        a0.z = fmaf(v0, xv0.z, a0.z); a0.w = fmaf(v0, xv0.w, a0.w);
        s0.x = fmaf(v0, xv0.x + pv0.x, s0.x); s0.y = fmaf(v0, xv0.y + pv0.y, s0.y);
        s0.z = fmaf(v0, xv0.z + pv0.z, s0.z); s0.w = fmaf(v0, xv0.w + pv0.w, s0.w);
        a1.x = fmaf(v1, xv1.x, a1.x); a1.y = fmaf(v1, xv1.y, a1.y);
        a1.z = fmaf(v1, xv1.z, a1.z); a1.w = fmaf(v1, xv1.w, a1.w);
        s1.x = fmaf(v1, xv1.x + pv1.x, s1.x); s1.y = fmaf(v1, xv1.y + pv1.y, s1.y);
        s1.z = fmaf(v1, xv1.z + pv1.z, s1.z); s1.w = fmaf(v1, xv1.w + pv1.w, s1.w);
    }
    if (e < end) {
        int2 p0 = g_epk[e];
        float v0 = __int_as_float(p0.y);
        size_t c0 = (size_t)p0.x * 128 + off;
        float4 xv0 = *(const float4*)(x + c0);
        float4 pv0 = *(const float4*)(perb + c0);
        a0.x = fmaf(v0, xv0.x, a0.x); a0.y = fmaf(v0, xv0.y, a0.y);
        a0.z = fmaf(v0, xv0.z, a0.z); a0.w = fmaf(v0, xv0.w, a0.w);
        s0.x = fmaf(v0, xv0.x + pv0.x, s0.x); s0.y = fmaf(v0, xv0.y + pv0.y, s0.y);
        s0.z = fmaf(v0, xv0.z + pv0.z, s0.z); s0.w = fmaf(v0, xv0.w + pv0.w, s0.w);
    }
    a0.x += a1.x; a0.y += a1.y; a0.z += a1.z; a0.w += a1.w;
    s0.x += s1.x; s0.y += s1.y; s0.z += s1.z; s0.w += s1.w;
    size_t ro = (size_t)r * 128 + off;
    *(float4*)(ax + ro) = a0;
    *(float4*)(as + ro) = s0;
}

// ---------------------------------------------------------------------------
// Pipelined tf32 GEMM, cp.async ping-pong, BK=32 x 4 chunks, 512 thr / 16 warps.
// PHASE 0 (5 sets): 0: TY=AX@Wt+bt       1: U1=AX@WW1+bb1 (stats0)
//                   2: TX=AS@Wt+bt       3: emb=AS@W+b+x+perb (no EX store)
//                   4: U2=AS@WW1+bb1 (stats1)
// PHASE 2 (2 sets): p=PReLU(BN(U))@W2+b2 (no store), fused BYOL loss vs T
// ---------------------------------------------------------------------------
#define AP_ 36
#define BP_ 136
#define ACH (128 * AP_)
#define BCH (32 * BP_)
#define RED_OFF (2 * ACH + 2 * BCH)
#define SMEM_BYTES ((RED_OFF + 384 + 256) * 4)

template <int PHASE>
__global__ __launch_bounds__(512, 2)
void fgemm(const float* __restrict__ AX, const float* __restrict__ AS,
           float* __restrict__ TY, float* __restrict__ TX,
           float* __restrict__ U1, float* __restrict__ U2,
           const float* __restrict__ b, const float* __restrict__ bt,
           const float* __restrict__ b2,
           const float* __restrict__ beta, const float* __restrict__ alphap,
           const float* __restrict__ xsrc, const float* __restrict__ psrc,
           float* __restrict__ emb, int n) {
    extern __shared__ float smf[];
    uint32_t sb = smem_u32(smf);
    float* redf = smf + RED_OFF;
    float* sG   = smf + RED_OFF + 384;
    float* sBp  = sG + 128;

    const int tid = threadIdx.x;
    const int wid = tid >> 5;
    const int lane = tid & 31;
    const int grp = lane >> 2;
    const int tig = lane & 3;
    const int wm = wid >> 1;
    const int wn = wid & 1;
    const int set = blockIdx.x;
    const int m0 = blockIdx.y * 128;

    const float* A;
    const float* Bm;
    const float* bias;
    float* outp = nullptr;
    const float* Tm = nullptr;
    bool do_emb = false, do_stats = false;
    int statset = 0;
    if (PHASE == 0) {
        A = (set >= 2) ? AS : AX;
        if (set == 0)      { Bm = g_w + DD * DD; bias = bt;    outp = TY; }
        else if (set == 1) { Bm = g_ww1;         bias = g_bb1; outp = U1; do_stats = true; statset = 0; }
        else if (set == 2) { Bm = g_w + DD * DD; bias = bt;    outp = TX; }
        else if (set == 3) { Bm = g_w;           bias = b;     outp = emb; do_emb = true; }
        else               { Bm = g_ww1;         bias = g_bb1; outp = U2; do_stats = true; statset = 1; }
    } else {
        A = set ? U2 : U1;
        Bm = g_w + 3 * DD * DD;
        bias = b2;
        Tm = set ? TY : TX;
    }

    if (tid < 384) redf[tid] = 0.f;
    float alpha = 0.f;
    if (PHASE == 2) {
        alpha = __ldg(alphap);
        if (tid < 128) {
            float mu = g_bnp[set * 256 + tid];
            float g  = g_bnp[set * 256 + 128 + tid];
            sG[tid] = g;
            sBp[tid] = beta[tid] - mu * g;
        }
    }

    float acc[8][4];
#pragma unroll
    for (int j = 0; j < 8; j++)
#pragma unroll
        for (int q = 0; q < 4; q++) acc[j][q] = 0.f;

    auto issue = [&](int c, int s) {
        const int kb = c * 32;
#pragma unroll
        for (int j = 0; j < 2; j++) {
            int f = tid + j * 512;
            int row = f >> 3, c4 = f & 7;
            uint32_t dst = sb + (uint32_t)((s * ACH + row * AP_ + c4 * 4) * 4);
            cp16(dst, A + (size_t)(m0 + row) * 128 + kb + c4 * 4, (m0 + row) < n);
        }
#pragma unroll
        for (int j = 0; j < 2; j++) {
            int f = tid + j * 512;
            int kr = f >> 5, c4 = f & 31;
            uint32_t dst = sb + (uint32_t)((2 * ACH + s * BCH + kr * BP_ + c4 * 4) * 4);
            cp16(dst, Bm + (size_t)(kb + kr) * 128 + c4 * 4, true);
        }
        CP_COMMIT();
    };

    issue(0, 0);
    for (int c = 0; c < 4; c++) {
        if (c < 3) {
            issue(c + 1, (c + 1) & 1);
            asm volatile("cp.async.wait_group 1;" ::: "memory");
        } else {
            asm volatile("cp.async.wait_group 0;" ::: "memory");
        }
        __syncthreads();
        const uint32_t* Ab = (const uint32_t*)(smf + (c & 1) * ACH);
        const uint32_t* Bb = (const uint32_t*)(smf + 2 * ACH + (c & 1) * BCH);
#pragma unroll
        for (int ks = 0; ks < 4; ks++) {
            const int k0 = ks * 8;
            const uint32_t* a0p = Ab + (wm * 16 + grp) * AP_ + k0 + tig;
            const uint32_t* a1p = a0p + 8 * AP_;
            uint32_t af0 = a0p[0], af1 = a1p[0], af2 = a0p[4], af3 = a1p[4];
            if (PHASE == 2) {
                int kA = c * 32 + k0 + tig;
                float gA = sG[kA], bA = sBp[kA];
                float gB = sG[kA + 4], bB = sBp[kA + 4];
                af0 = bnfrag(af0, gA, bA, alpha);
                af1 = bnfrag(af1, gA, bA, alpha);
                af2 = bnfrag(af2, gB, bB, alpha);
                af3 = bnfrag(af3, gB, bB, alpha);
            } else {
                af0 = rndu(af0); af1 = rndu(af1);
                af2 = rndu(af2); af3 = rndu(af3);
            }
#pragma unroll
            for (int ni = 0; ni < 8; ni++) {
                const uint32_t* bp = Bb + (k0 + tig) * BP_ + wn * 64 + ni * 8 + grp;
                uint32_t b0 = bp[0], b1v = bp[4 * BP_];
                mma_tf32(acc[ni][0], acc[ni][1], acc[ni][2], acc[ni][3],
                         af0, af1, af2, af3, b0, b1v);
            }
        }
        __syncthreads();
    }

    const int r0 = m0 + wm * 16 + grp;
    const int r1 = r0 + 8;
    const bool ok0 = r0 < n, ok1 = r1 < n;

    if (PHASE == 2) {
        float pp0 = 0.f, tt0 = 0.f, pt0 = 0.f;
        float pp1 = 0.f, tt1 = 0.f, pt1 = 0.f;
#pragma unroll
        for (int ni = 0; ni < 8; ni++) {
            int col = wn * 64 + ni * 8 + tig * 2;
            float2 bv = *(const float2*)(bias + col);
            float c0 = acc[ni][0] + bv.x, c1 = acc[ni][1] + bv.y;
            float c2 = acc[ni][2] + bv.x, c3 = acc[ni][3] + bv.y;
            if (ok0) {
                float2 t = *(const float2*)(Tm + (size_t)r0 * 128 + col);
                pp0 += c0 * c0 + c1 * c1;
                tt0 += t.x * t.x + t.y * t.y;
                pt0 += c0 * t.x + c1 * t.y;
            }
            if (ok1) {
                float2 t = *(const float2*)(Tm + (size_t)r1 * 128 + col);
                pp1 += c2 * c2 + c3 * c3;
                tt1 += t.x * t.x + t.y * t.y;
                pt1 += c2 * t.x + c3 * t.y;
            }
        }
#pragma unroll
        for (int msk = 1; msk <= 2; msk <<= 1) {
            pp0 += __shfl_xor_sync(0xffffffffu, pp0, msk);
            tt0 += __shfl_xor_sync(0xffffffffu, tt0, msk);
            pt0 += __shfl_xor_sync(0xffffffffu, pt0, msk);
            pp1 += __shfl_xor_sync(0xffffffffu, pp1, msk);
            tt1 += __shfl_xor_sync(0xffffffffu, tt1, msk);
            pt1 += __shfl_xor_sync(0xffffffffu, pt1, msk);
        }
        if (tig == 0) {
            int lr0 = wm * 16 + grp, lr1 = lr0 + 8;
            atomicAdd(&redf[lr0], pp0);
            atomicAdd(&redf[128 + lr0], tt0);
            atomicAdd(&redf[256 + lr0], pt0);
            atomicAdd(&redf[lr1], pp1);
            atomicAdd(&redf[128 + lr1], tt1);
            atomicAdd(&redf[256 + lr1], pt1);
        }
        __syncthreads();
        if (tid < 128) {
            float l = 0.f;
            if (m0 + tid < n)
                l = 2.f - 2.f * redf[256 + tid] * rsqrtf(redf[tid]) * rsqrtf(redf[128 + tid]);
#pragma unroll
            for (int o = 16; o; o >>= 1) l += __shfl_xor_sync(0xffffffffu, l, o);
            if (lane == 0) redf[320 + wid] = l;
        }
        __syncthreads();
        if (tid == 0)
            atomicAdd(&g_loss, redf[320] + redf[321] + redf[322] + redf[323]);
        return;
    }

    // PHASE 0 store epilogue
#pragma unroll
    for (int ni = 0; ni < 8; ni++) {
        int col = wn * 64 + ni * 8 + tig * 2;
        float2 bv = *(const float2*)(bias + col);
        float c0 = acc[ni][0] + bv.x, c1 = acc[ni][1] + bv.y;
        float c2 = acc[ni][2] + bv.x, c3 = acc[ni][3] + bv.y;
        if (ok0) {
            size_t o0 = (size_t)r0 * 128 + col;
            if (do_emb) {
                float2 xv = *(const float2*)(xsrc + o0);
                float2 pv = *(const float2*)(psrc + o0);
                *(float2*)(outp + o0) = make_float2(c0 + xv.x + pv.x, c1 + xv.y + pv.y);
            } else {
                *(float2*)(outp + o0) = make_float2(c0, c1);
            }
        }
        if (ok1) {
            size_t o1 = (size_t)r1 * 128 + col;
            if (do_emb) {
                float2 xv = *(const float2*)(xsrc + o1);
                float2 pv = *(const float2*)(psrc + o1);
                *(float2*)(outp + o1) = make_float2(c2 + xv.x + pv.x, c3 + xv.y + pv.y);
            } else {
                *(float2*)(outp + o1) = make_float2(c2, c3);
            }
        }
        if (do_stats) {
            float s0 = (ok0 ? c0 : 0.f) + (ok1 ? c2 : 0.f);
            float s1 = (ok0 ? c1 : 0.f) + (ok1 ? c3 : 0.f);
            float q0 = (ok0 ? c0 * c0 : 0.f) + (ok1 ? c2 * c2 : 0.f);
            float q1 = (ok0 ? c1 * c1 : 0.f) + (ok1 ? c3 * c3 : 0.f);
#pragma unroll
            for (int msk = 4; msk <= 16; msk <<= 1) {
                s0 += __shfl_xor_sync(0xffffffffu, s0, msk);
                s1 += __shfl_xor_sync(0xffffffffu, s1, msk);
                q0 += __shfl_xor_sync(0xffffffffu, q0, msk);
                q1 += __shfl_xor_sync(0xffffffffu, q1, msk);
            }
            if (grp == 0) {
                atomicAdd(&redf[col], s0);
                atomicAdd(&redf[col + 1], s1);
                atomicAdd(&redf[128 + col], q0);
                atomicAdd(&redf[128 + col + 1], q1);
            }
        }
    }

    if (do_stats) {
        __syncthreads();
        if (tid < 256)
            atomicAdd(&g_stats[statset * 256 + tid], redf[tid]);
    }
}

// ---------------------------------------------------------------------------
__global__ void bn_finalize(const float* __restrict__ gamma, int n) {
    int t = threadIdx.x;
    int set = t >> 7, c = t & 127;
    float s = g_stats[set * 256 + c];
    float q = g_stats[set * 256 + 128 + c];
    float mu = s / (float)n;
    float var = q / (float)n - mu * mu;
    float g = gamma[c] * rsqrtf(var + 1e-5f);
    g_bnp[set * 256 + c] = mu;
    g_bnp[set * 256 + 128 + c] = g;
}

__global__ void finish_kernel(float* __restrict__ out, int n, size_t idx) {
    out[idx] = g_loss / (float)n;
}

// ---------------------------------------------------------------------------
extern "C" void kernel_launch(void* const* d_in, const int* in_sizes, int n_in,
                              void* d_out, int out_size) {
    const float* x     = (const float*)d_in[0];
    const float* perb  = (const float*)d_in[1];
    const int*   erow  = (const int*)d_in[2];
    const int*   ecol  = (const int*)d_in[3];
    const float* eval  = (const float*)d_in[4];
    const float* W     = (const float*)d_in[5];
    const float* b     = (const float*)d_in[6];
    const float* Wt    = (const float*)d_in[7];
    const float* bt    = (const float*)d_in[8];
    const float* W1    = (const float*)d_in[9];
    const float* b1    = (const float*)d_in[10];
    const float* gamma = (const float*)d_in[11];
    const float* beta  = (const float*)d_in[12];
    const float* alpha = (const float*)d_in[13];
    const float* W2    = (const float*)d_in[14];
    const float* b2    = (const float*)d_in[15];

    const int n = in_sizes[0] / DD;
    const int E = in_sizes[2];
    float* out = (float*)d_out;

    float* buf = nullptr;
    cudaGetSymbolAddress((void**)&buf, g_buf);

    float* AX  = buf + 0 * NB;   // adj@x
    float* AS  = buf + 1 * NB;   // adj@(x+perb)
    float* TY  = buf + 2 * NB;   // target_y
    float* TX  = buf + 3 * NB;   // target_x
    float* U1  = buf + 4 * NB;
    float* U2  = buf + 5 * NB;

    cudaFuncSetAttribute(fgemm<0>, cudaFuncAttributeMaxDynamicSharedMemorySize, SMEM_BYTES);
    cudaFuncSetAttribute(fgemm<2>, cudaFuncAttributeMaxDynamicSharedMemorySize, SMEM_BYTES);

    // init + composed weights + CSR build (two-level scan)
    init_kernel<<<(n + 1 + 255) / 256, 256>>>(W, Wt, W1, W2, n);
    wprod_kernel<<<64, 256>>>(b, b1);
    hist_kernel<<<(E + 255) / 256, 256>>>(erow, E);
    const int nblk = (n + 1 + 1023) / 1024;
    scanA_kernel<<<nblk, 1024>>>(n);
    scanB_kernel<<<1, 64>>>(nblk);
    scanC_kernel<<<nblk, 1024>>>(n);
    scatter_kernel<<<(E + 255) / 256, 256>>>(erow, ecol, eval, E);

    // gather-only SpMM (no atomics)
    spmm_csr<<<(int)(((long long)n * 32 + 255) / 256), 256>>>(x, perb, AX, AS, n);

    const int gbx = (n + 127) / 128;
    dim3 g5(5, gbx, 1), g2(2, gbx, 1);

    // merged encoder + predictor L1: TY, U1(stats), TX, emb, U2(stats)
    fgemm<0><<<g5, 512, SMEM_BYTES>>>(AX, AS, TY, TX, U1, U2,
                                      b, bt, b2, beta, alpha, x, perb, out, n);
    bn_finalize<<<1, 256>>>(gamma, n);
    // predictor L2 (fused BN+PReLU) + fused BYOL loss
    fgemm<2><<<g2, 512, SMEM_BYTES>>>(AX, AS, TY, TX, U1, U2,
                                      b, bt, b2, beta, alpha, x, perb, out, n);

    finish_kernel<<<1, 1>>>(out, n, (size_t)n * DD);
}